// round 13
// baseline (speedup 1.0000x reference)
#include <cuda_runtime.h>
#include <math.h>

#define Bq   32
#define Tt   1024
#define Dd   512
#define Hh   512
#define Vv   64
#define Ss   128
#define KK2  1024
#define G4   2048
#define NBLK 128
#define NTHR 512
#define PIT  1028

typedef unsigned long long ull;

// smem layout (float offsets)
#define OFF_A    0       /* 32896: P1 sX[32][1028]+sp; P2 TMA slots 16x2048 + s_pv */
#define OFF_B    32896   /* sW[16][1028] — staged ONCE */
#define OFF_ONE  49344
#define OFF_BIAS 50368
#define OFF_H    50384   /* 512  */
#define OFF_HC   50896   /* 1024 */
#define OFF_PM   51920
#define OFF_PS   51936
#define OFF_WGT  51952
#define OFF_LOG  51968
#define OFF_MS   52032
#define OFF_E    52036   /* 256 */
#define OFF_IDX  52292   /* 32 ints */
#define OFF_MB   52324   /* 64 floats: 16 warps x 2 mbarriers (8B each) */
#define SMEM_FLOATS 52388

// ---------------- device scratch ----------------
__device__ float g_xh2[Bq][KK2];
__device__ float g_logits[Bq][Vv];      // raw logits of current step
__device__ float g_c[2][Bq][Hh];
__device__ float g_gates[Bq][G4];
__device__ float g_pm[Bq * 4];
__device__ float g_ps[Bq * 4];
__device__ float g_pvm[Bq][4][Dd];
__device__ float g_e0[Bq][256];
__device__ unsigned g_bcnt[Bq];

__device__ unsigned g_cntA[Bq];
__device__ unsigned g_cntB = 0;
__device__ volatile unsigned g_gen = 0;

__device__ __forceinline__ void grid_sync(int b) {
    __threadfence();
    __syncthreads();
    if (threadIdx.x == 0) {
        unsigned gen = g_gen;
        if (atomicAdd(&g_cntA[b], 1u) == 3u) {
            atomicExch(&g_cntA[b], 0u);
            if (atomicAdd(&g_cntB, 1u) == 31u) {
                atomicExch(&g_cntB, 0u);
                __threadfence();
                g_gen = gen + 1;
            }
        }
        while (g_gen == gen) __nanosleep(16);
        __threadfence();
    }
    __syncthreads();
}

__device__ __forceinline__ ull fma2(ull a, ull b, ull c) {
    ull d; asm("fma.rn.f32x2 %0,%1,%2,%3;" : "=l"(d) : "l"(a), "l"(b), "l"(c));
    return d;
}
__device__ __forceinline__ ull mul2(ull a, ull b) {
    ull d; asm("mul.rn.f32x2 %0,%1,%2;" : "=l"(d) : "l"(a), "l"(b));
    return d;
}
__device__ __forceinline__ ull pk2(float x, float y) {
    ull d; asm("mov.b64 %0,{%1,%2};" : "=l"(d) : "f"(x), "f"(y));
    return d;
}
__device__ __forceinline__ float2 unpk(ull v) {
    float2 r; asm("mov.b64 {%0,%1},%2;" : "=f"(r.x), "=f"(r.y) : "l"(v));
    return r;
}
__device__ __forceinline__ float wsum(float v) {
#pragma unroll
    for (int o = 16; o; o >>= 1) v += __shfl_xor_sync(0xffffffffu, v, o);
    return v;
}
__device__ __forceinline__ float wmax(float v) {
#pragma unroll
    for (int o = 16; o; o >>= 1) v = fmaxf(v, __shfl_xor_sync(0xffffffffu, v, o));
    return v;
}
__device__ __forceinline__ float fsig(float x) {
    return __fdividef(1.f, 1.f + __expf(-x));
}
__device__ __forceinline__ float ftanh(float x) {
    return 1.f - __fdividef(2.f, __expf(2.f * x) + 1.f);
}
__device__ __forceinline__ float ldcv(const float* p) {
    float v; asm("ld.global.cv.f32 %0,[%1];" : "=f"(v) : "l"(p));
    return v;
}
__device__ __forceinline__ float4 ldcv4(const float4* p) {
    float4 v;
    asm("ld.global.cv.v4.f32 {%0,%1,%2,%3},[%4];"
        : "=f"(v.x), "=f"(v.y), "=f"(v.z), "=f"(v.w) : "l"(p));
    return v;
}
// ---- TMA bulk-copy + mbarrier helpers ----
__device__ __forceinline__ unsigned smem_u32(const void* p) {
    unsigned r;
    asm("{ .reg .u64 t; cvta.to.shared.u64 t, %1; cvt.u32.u64 %0, t; }"
        : "=r"(r) : "l"(p));
    return r;
}
__device__ __forceinline__ void mbar_init(unsigned mbar, unsigned cnt) {
    asm volatile("mbarrier.init.shared.b64 [%0], %1;" :: "r"(mbar), "r"(cnt) : "memory");
}
__device__ __forceinline__ void mbar_expect(unsigned mbar, unsigned bytes) {
    asm volatile("mbarrier.arrive.expect_tx.shared.b64 _, [%0], %1;"
                 :: "r"(mbar), "r"(bytes) : "memory");
}
__device__ __forceinline__ void bulk_copy(unsigned dst, const void* src,
                                          unsigned bytes, unsigned mbar) {
    asm volatile("cp.async.bulk.shared::cluster.global.mbarrier::complete_tx::bytes "
                 "[%0], [%1], %2, [%3];"
                 :: "r"(dst), "l"(src), "r"(bytes), "r"(mbar) : "memory");
}
__device__ __forceinline__ void mbar_wait(unsigned mbar, unsigned parity) {
    asm volatile(
        "{\n\t.reg .pred P;\n\t"
        "WL%=:\n\t"
        "mbarrier.try_wait.parity.acquire.cta.shared::cta.b64 P, [%0], %1;\n\t"
        "@!P bra WL%=;\n\t}"
        :: "r"(mbar), "r"(parity) : "memory");
}
__device__ __forceinline__ void fence_async() {
    asm volatile("fence.proxy.async;" ::: "memory");
}

__global__ void __launch_bounds__(NTHR, 1) speller_kernel(
    const float* __restrict__ L,
    const float* __restrict__ W_ih,
    const float* __restrict__ W_hh,
    const float* __restrict__ b_ih,
    const float* __restrict__ b_hh,
    const float* __restrict__ W_out,
    const float* __restrict__ b_out,
    float* __restrict__ out_logp,
    float* __restrict__ out_attn)
{
    const int tid  = threadIdx.x;
    const int bid  = blockIdx.x;
    const int wid  = tid >> 5;
    const int lane = tid & 31;
    const int b    = bid >> 2, part = bid & 3;

    extern __shared__ float sm[];
    float* s_h      = sm + OFF_H;
    float* s_hc     = sm + OFF_HC;
    float* s_pm     = sm + OFF_PM;
    float* s_ps     = sm + OFF_PS;
    float* s_wgt    = sm + OFF_WGT;
    float* s_MS     = sm + OFF_MS;
    float* s_e      = sm + OFF_E;
    int*   s_idx    = (int*)(sm + OFF_IDX);
    float* s_one    = sm + OFF_ONE;
    float* s_bias   = sm + OFF_BIAS;

    const unsigned mb0   = smem_u32(sm + OFF_MB) + wid * 16;
    const unsigned mb1   = mb0 + 8;
    const unsigned slotB = smem_u32(sm) + wid * 8192;

    if (lane == 0) { mbar_init(mb0, 1); mbar_init(mb1, 1); fence_async(); }

    // ---------------- init ----------------
    for (int i = bid * NTHR + tid; i < Bq * Hh; i += NBLK * NTHR)
        (&g_c[0][0][0])[i] = 0.f;
    for (int i = bid * NTHR + tid; i < Bq * KK2; i += NBLK * NTHR) {
        int bb = i >> 10, k = i & 1023;
        g_xh2[bb][k] = (k < 512) ? L[(size_t)bb * Tt * Dd + k] : 0.f;
    }
    if (part == 0 && tid == 0) g_bcnt[b] = 0;

    // stage W rows ONCE
    {
        float4* sW4 = (float4*)(sm + OFF_B);
        const float4* wi4 = (const float4*)W_ih + (size_t)(bid * 16) * 144;
        const float4* wh4 = (const float4*)W_hh + (size_t)(bid * 16) * 128;
        for (int idx = tid; idx < 16 * 128; idx += NTHR) {
            int jj = idx >> 7, c = idx & 127;
            sW4[jj * 257 + c]       = wi4[jj * 144 + 16 + c];
            sW4[jj * 257 + 128 + c] = wh4[idx];
        }
        for (int idx = tid; idx < 16 * 16; idx += NTHR) {
            int jj = idx >> 4, c = idx & 15;
            ((float4*)s_one)[jj * 16 + c] = wi4[jj * 144 + c];
        }
        if (tid < 16) {
            int j = bid * 16 + tid;
            s_bias[tid] = b_ih[j] + b_hh[j];
        }
    }
    grid_sync(b);

    const int gtype = bid >> 5;

    for (int s = 0; s < Ss; ++s) {
        const int crd = s & 1, cwr = crd ^ 1;

        // ========== P1: prologue (argmax + prev logp) + gates GEMM ==========
        {
            const float4* src = (const float4*)(&g_xh2[0][0]);
            float4* sX4 = (float4*)sm;
            for (int idx = tid; idx < 32 * 256; idx += NTHR) {
                int bb = idx >> 8, c = idx & 255;
                sX4[bb * 257 + c] = ldcv4(src + idx);
            }
            // deferred argmax of prev step's logits: warp w -> batches 2w,2w+1
            if (s > 0) {
#pragma unroll
                for (int u = 0; u < 2; ++u) {
                    const int bb = 2 * wid + u;
                    float z0 = ldcv(&g_logits[bb][lane]);
                    float z1 = ldcv(&g_logits[bb][32 + lane]);
                    float bv; int bi2;
                    if (z1 > z0) { bv = z1; bi2 = 32 + lane; }
                    else         { bv = z0; bi2 = lane; }
#pragma unroll
                    for (int o = 16; o; o >>= 1) {
                        float ov = __shfl_xor_sync(0xffffffffu, bv, o);
                        int   oi = __shfl_xor_sync(0xffffffffu, bi2, o);
                        if (ov > bv || (ov == bv && oi < bi2)) { bv = ov; bi2 = oi; }
                    }
                    if (lane == 0) s_idx[bb] = bi2;
                    if (part == 1 && bb == b) {      // logp for step s-1
                        float zm = wmax(fmaxf(z0, z1));
                        float es = wsum(__expf(z0 - zm) + __expf(z1 - zm));
                        float lse = zm + __logf(es);
                        float* lp = out_logp + ((size_t)(s - 1) * Bq + b) * Vv;
                        lp[lane]      = z0 - lse;
                        lp[32 + lane] = z1 - lse;
                    }
                }
            } else {
                if (tid < 32) s_idx[tid] = 0;
            }
            __syncthreads();

            const int jg2 = lane & 3, bg = lane >> 2;
            const float* wb0 = sm + OFF_B + jg2 * PIT + wid * 64;
            const float* xb0 = sm + bg * PIT + wid * 64;

            ull acc[4][4];
#pragma unroll
            for (int jj = 0; jj < 4; ++jj)
#pragma unroll
                for (int bb = 0; bb < 4; ++bb) acc[jj][bb] = 0ull;

#pragma unroll 4
            for (int kq = 0; kq < 16; ++kq) {
                const int off = kq * 4;
                ulonglong2 wv0 = *(const ulonglong2*)(wb0 + off);
                ulonglong2 wv1 = *(const ulonglong2*)(wb0 + 4 * PIT + off);
                ulonglong2 wv2 = *(const ulonglong2*)(wb0 + 8 * PIT + off);
                ulonglong2 wv3 = *(const ulonglong2*)(wb0 + 12 * PIT + off);
                ulonglong2 xv0 = *(const ulonglong2*)(xb0 + off);
                ulonglong2 xv1 = *(const ulonglong2*)(xb0 + 8 * PIT + off);
                ulonglong2 xv2 = *(const ulonglong2*)(xb0 + 16 * PIT + off);
                ulonglong2 xv3 = *(const ulonglong2*)(xb0 + 24 * PIT + off);
#define P1STEP(jj, wv) \
                acc[jj][0] = fma2(wv.x, xv0.x, acc[jj][0]); \
                acc[jj][0] = fma2(wv.y, xv0.y, acc[jj][0]); \
                acc[jj][1] = fma2(wv.x, xv1.x, acc[jj][1]); \
                acc[jj][1] = fma2(wv.y, xv1.y, acc[jj][1]); \
                acc[jj][2] = fma2(wv.x, xv2.x, acc[jj][2]); \
                acc[jj][2] = fma2(wv.y, xv2.y, acc[jj][2]); \
                acc[jj][3] = fma2(wv.x, xv3.x, acc[jj][3]); \
                acc[jj][3] = fma2(wv.y, xv3.y, acc[jj][3]);
                P1STEP(0, wv0)
                P1STEP(1, wv1)
                P1STEP(2, wv2)
                P1STEP(3, wv3)
#undef P1STEP
            }
            __syncthreads();
            float* sp = sm + wid * 640;
#pragma unroll
            for (int jj = 0; jj < 4; ++jj)
#pragma unroll
                for (int bb = 0; bb < 4; ++bb) {
                    float2 p = unpk(acc[jj][bb]);
                    const int j = jg2 + 4 * jj, bcol = bg + 8 * bb;
                    sp[j * 40 + bcol] = p.x + p.y;
                }
            __syncthreads();
            {
                float v = 0.f;
#pragma unroll
                for (int q = 0; q < 16; ++q)
                    v += sm[q * 640 + wid * 40 + lane];
                v += s_one[wid * 64 + s_idx[lane]] + s_bias[wid];
                float act = (gtype == 2) ? ftanh(v) : fsig(v);
                g_gates[lane][bid * 16 + wid] = act;
            }
        }
        grid_sync(b);

        // ========== P2: TMA-pipelined flash attention ==========
        {
            const char* Lb = (const char*)L + (size_t)b * Tt * Dd * 4;
            const int t0 = part * 256 + wid * 16;
            const char* srcBase = Lb + (size_t)t0 * 2048;

            if (lane == 0) {
                mbar_expect(mb0, 4096); bulk_copy(slotB,        srcBase,        4096, mb0);
                mbar_expect(mb1, 4096); bulk_copy(slotB + 4096, srcBase + 4096, 4096, mb1);
            }
            __syncwarp();

            {   // cell update with pre-activated gates
                const int k = tid;
                float iv = ldcv(&g_gates[b][k]);
                float fv = ldcv(&g_gates[b][512 + k]);
                float gv = ldcv(&g_gates[b][1024 + k]);
                float ov = ldcv(&g_gates[b][1536 + k]);
                float cp = ldcv(&g_c[crd][b][k]);
                float cn = fv * cp + iv * gv;
                float hn = ov * ftanh(cn);
                s_h[k] = hn;
                if (part == 0) { g_c[cwr][b][k] = cn; g_xh2[b][512 + k] = hn; }
            }
            __syncthreads();

            ull H[8];
            {
                const ulonglong2* h2 = (const ulonglong2*)s_h;
#pragma unroll
                for (int q = 0; q < 4; ++q) {
                    ulonglong2 t2 = h2[lane + (q << 5)];
                    H[2 * q] = t2.x; H[2 * q + 1] = t2.y;
                }
            }
            float m = -INFINITY, ss = 0.f;
            ull V[8];
#pragma unroll
            for (int q = 0; q < 8; ++q) V[q] = 0ull;

            const float* slotF = sm + wid * 2048;

#pragma unroll
            for (int st = 0; st < 8; ++st) {
                const unsigned mb = (st & 1) ? mb1 : mb0;
                mbar_wait(mb, (st >> 1) & 1);
                const ulonglong2* bufU2 =
                    (const ulonglong2*)(slotF + (st & 1) * 1024);

                ulonglong2 a0 = bufU2[lane];
                ulonglong2 a1 = bufU2[32 + lane];
                ulonglong2 a2 = bufU2[64 + lane];
                ulonglong2 a3 = bufU2[96 + lane];
                ulonglong2 b0 = bufU2[128 + lane];
                ulonglong2 b1 = bufU2[160 + lane];
                ulonglong2 b2 = bufU2[192 + lane];
                ulonglong2 b3 = bufU2[224 + lane];

                ull ea2 = mul2(a0.x, H[0]);
                ull eb2 = mul2(b0.x, H[0]);
                ea2 = fma2(a0.y, H[1], ea2); eb2 = fma2(b0.y, H[1], eb2);
                ea2 = fma2(a1.x, H[2], ea2); eb2 = fma2(b1.x, H[2], eb2);
                ea2 = fma2(a1.y, H[3], ea2); eb2 = fma2(b1.y, H[3], eb2);
                ea2 = fma2(a2.x, H[4], ea2); eb2 = fma2(b2.x, H[4], eb2);
                ea2 = fma2(a2.y, H[5], ea2); eb2 = fma2(b2.y, H[5], eb2);
                ea2 = fma2(a3.x, H[6], ea2); eb2 = fma2(b3.x, H[6], eb2);
                ea2 = fma2(a3.y, H[7], ea2); eb2 = fma2(b3.y, H[7], eb2);

                float2 fa = unpk(ea2), fb = unpk(eb2);
                float ea = fa.x + fa.y, eb = fb.x + fb.y;
#pragma unroll
                for (int o = 16; o; o >>= 1) {
                    ea += __shfl_xor_sync(0xffffffffu, ea, o);
                    eb += __shfl_xor_sync(0xffffffffu, eb, o);
                }
                if (lane == 0) {
                    s_e[wid * 16 + 2 * st]     = ea;
                    s_e[wid * 16 + 2 * st + 1] = eb;
                }

                float m_new = fmaxf(m, fmaxf(ea, eb));
                float wa = __expf(ea - m_new);
                float wb = __expf(eb - m_new);
                if (m_new > m) {
                    float sc = __expf(m - m_new);
                    ss = ss * sc;
                    ull sc2 = pk2(sc, sc);
#pragma unroll
                    for (int q = 0; q < 8; ++q) V[q] = mul2(V[q], sc2);
                    m = m_new;
                }
                ss += wa + wb;
                ull wa2 = pk2(wa, wa), wb2 = pk2(wb, wb);
                V[0] = fma2(a0.x, wa2, V[0]); V[0] = fma2(b0.x, wb2, V[0]);
                V[1] = fma2(a0.y, wa2, V[1]); V[1] = fma2(b0.y, wb2, V[1]);
                V[2] = fma2(a1.x, wa2, V[2]); V[2] = fma2(b1.x, wb2, V[2]);
                V[3] = fma2(a1.y, wa2, V[3]); V[3] = fma2(b1.y, wb2, V[3]);
                V[4] = fma2(a2.x, wa2, V[4]); V[4] = fma2(b2.x, wb2, V[4]);
                V[5] = fma2(a2.y, wa2, V[5]); V[5] = fma2(b2.y, wb2, V[5]);
                V[6] = fma2(a3.x, wa2, V[6]); V[6] = fma2(b3.x, wb2, V[6]);
                V[7] = fma2(a3.y, wa2, V[7]); V[7] = fma2(b3.y, wb2, V[7]);

                __syncwarp();
                if (lane == 0 && st + 2 < 8) {
                    mbar_expect(mb, 4096);
                    bulk_copy(slotB + (st & 1) * 4096,
                              srcBase + (size_t)(st + 2) * 4096, 4096, mb);
                }
            }

            __syncthreads();
            float* s_pv = sm;
            {
                ulonglong2* pv2 = (ulonglong2*)(s_pv + (wid << 9));
#pragma unroll
                for (int q = 0; q < 4; ++q) {
                    ulonglong2 t2; t2.x = V[2 * q]; t2.y = V[2 * q + 1];
                    pv2[lane + (q << 5)] = t2;
                }
                if (lane == 0) { s_pm[wid] = m; s_ps[wid] = ss; }
            }
            __syncthreads();
            if (wid == 0) {
                float mi = (lane < 16) ? s_pm[lane] : -INFINITY;
                float M = wmax(mi);
                float wg = (lane < 16) ? __expf(mi - M) : 0.f;
                if (lane < 16) s_wgt[lane] = wg;
                float sw = wsum((lane < 16) ? s_ps[lane] * wg : 0.f);
                if (lane == 0) { g_pm[b * 4 + part] = M; g_ps[b * 4 + part] = sw; }
            }
            if (part == 0 && tid >= 256) g_e0[b][tid - 256] = s_e[tid - 256];
            __syncthreads();
            {
                float acc = 0.f;
#pragma unroll
                for (int w = 0; w < 16; ++w)
                    acc += s_wgt[w] * s_pv[(w << 9) + tid];
                g_pvm[b][part][tid] = acc;
            }

            // ----- local sync among the 4 blocks of this batch -----
            __threadfence();
            __syncthreads();
            if (tid == 0) {
                atomicAdd(&g_bcnt[b], 1u);
                const unsigned tgt = 4u * (unsigned)(s + 1);
                while (((volatile unsigned*)g_bcnt)[b] < tgt) __nanosleep(16);
                __threadfence();
            }
            __syncthreads();

            // ----- merged P3: global merge, record, head (part0, raw logits) -----
            if (wid == 0) {
                float mi = (lane < 4) ? ldcv(&g_pm[b * 4 + lane]) : -INFINITY;
                float M = wmax(mi);
                float wg = (lane < 4) ? __expf(mi - M) : 0.f;
                if (lane < 4) s_wgt[lane] = wg;
                float S = wsum((lane < 4) ? ldcv(&g_ps[b * 4 + lane]) * wg : 0.f);
                if (lane == 0) { s_MS[0] = M; s_MS[1] = __fdividef(1.f, S); }
            }
            __syncthreads();
            const float M = s_MS[0], invS = s_MS[1];
            float* rec = out_attn + ((size_t)s * Bq + b) * Tt;

            if (part != 0) {
                if (tid < 256)
                    rec[part * 256 + tid] = __expf(s_e[tid] - M) * invS;
                if (part == 1 && tid >= 256)
                    rec[tid - 256] = __expf(ldcv(&g_e0[b][tid - 256]) - M) * invS;
            } else {
                {
                    const int d = tid;
                    float acc = s_wgt[0] * ldcv(&g_pvm[b][0][d])
                              + s_wgt[1] * ldcv(&g_pvm[b][1][d])
                              + s_wgt[2] * ldcv(&g_pvm[b][2][d])
                              + s_wgt[3] * ldcv(&g_pvm[b][3][d]);
                    float ctx = acc * invS;
                    s_hc[Hh + d] = ctx;
                    g_xh2[b][d] = ctx;
                    s_hc[d] = s_h[d];
                }
                __syncthreads();
                {   // raw logits only — softmax/argmax/logp deferred to next P1
                    ull C[16];
                    const ulonglong2* hc2 = (const ulonglong2*)s_hc;
#pragma unroll
                    for (int q = 0; q < 8; ++q) {
                        ulonglong2 t2 = hc2[lane + (q << 5)];
                        C[2 * q] = t2.x; C[2 * q + 1] = t2.y;
                    }
#pragma unroll
                    for (int rr = 0; rr < 4; ++rr) {
                        const int r = (wid << 2) | rr;
                        const ulonglong2* wr = (const ulonglong2*)(W_out + (size_t)r * 2 * Hh);
                        ull e2 = 0ull;
#pragma unroll
                        for (int q = 0; q < 8; ++q) {
                            ulonglong2 w2 = wr[lane + (q << 5)];
                            e2 = fma2(w2.x, C[2 * q], e2);
                            e2 = fma2(w2.y, C[2 * q + 1], e2);
                        }
                        float2 p = unpk(e2);
                        float v = wsum(p.x + p.y);
                        if (lane == 0) g_logits[b][r] = v + b_out[r];
                    }
                }
            }
        }
        grid_sync(b);
    }

    // ---------------- epilogue: logp for the last step (s = 127) ----------------
    if (part == 1 && wid == 0) {
        float z0 = ldcv(&g_logits[b][lane]);
        float z1 = ldcv(&g_logits[b][32 + lane]);
        float zm = wmax(fmaxf(z0, z1));
        float es = wsum(__expf(z0 - zm) + __expf(z1 - zm));
        float lse = zm + __logf(es);
        float* lp = out_logp + ((size_t)(Ss - 1) * Bq + b) * Vv;
        lp[lane]      = z0 - lse;
        lp[32 + lane] = z1 - lse;
    }
}

extern "C" void kernel_launch(void* const* d_in, const int* in_sizes, int n_in,
                              void* d_out, int out_size) {
    const float* L     = (const float*)d_in[0];
    const float* W_ih  = (const float*)d_in[1];
    const float* W_hh  = (const float*)d_in[2];
    const float* b_ih  = (const float*)d_in[3];
    const float* b_hh  = (const float*)d_in[4];
    const float* W_out = (const float*)d_in[5];
    const float* b_out = (const float*)d_in[6];
    float* out_logp = (float*)d_out;
    float* out_attn = (float*)d_out + (size_t)Ss * Bq * Vv;
    const int smem_bytes = SMEM_FLOATS * 4;
    cudaFuncSetAttribute(speller_kernel,
                         cudaFuncAttributeMaxDynamicSharedMemorySize, smem_bytes);
    speller_kernel<<<NBLK, NTHR, smem_bytes>>>(L, W_ih, W_hh, b_ih, b_hh,
                                               W_out, b_out, out_logp, out_attn);
}

// round 14
// speedup vs baseline: 1.1123x; 1.1123x over previous
#include <cuda_runtime.h>
#include <math.h>

#define Bq   32
#define Tt   1024
#define Dd   512
#define Hh   512
#define Vv   64
#define Ss   128
#define KK2  1024
#define G4   2048
#define NBLK 128
#define NTHR 512
#define PIT  1028

typedef unsigned long long ull;

// smem layout (float offsets)
#define OFF_A    0       /* 32896: P1 sX[32][1028]+sp; P2 TMA slots 16x2048 + s_pv */
#define OFF_B    32896   /* sW[16][1028] — staged ONCE */
#define OFF_ONE  49344
#define OFF_BIAS 50368
#define OFF_H    50384   /* 512  */
#define OFF_HC   50896   /* 1024 */
#define OFF_PM   51920
#define OFF_PS   51936
#define OFF_WGT  51952
#define OFF_LOG  51968
#define OFF_MS   52032
#define OFF_E    52036   /* 256 */
#define OFF_IDX  52292   /* 32 ints */
#define OFF_MB   52324   /* 64 floats: 16 warps x 2 mbarriers (8B each) */
#define SMEM_FLOATS 52388

// ---------------- device scratch ----------------
__device__ float g_xh2[Bq][KK2];
__device__ int   g_argmax[Bq];
__device__ float g_c[2][Bq][Hh];
__device__ float g_gates[Bq][G4];
__device__ float g_pm[Bq * 4];
__device__ float g_ps[Bq * 4];
__device__ float g_pvm[Bq][4][Dd];
__device__ float g_e0[Bq][256];
__device__ unsigned g_bcnt[Bq];

__device__ unsigned g_cntA[Bq];
__device__ unsigned g_cntB = 0;
__device__ volatile unsigned g_gen = 0;
__device__ unsigned g_ctx_cnt = 0;      // relaxed end-of-step: 32 part0 producers

__device__ __forceinline__ void grid_sync(int b) {
    __threadfence();
    __syncthreads();
    if (threadIdx.x == 0) {
        unsigned gen = g_gen;
        if (atomicAdd(&g_cntA[b], 1u) == 3u) {
            atomicExch(&g_cntA[b], 0u);
            if (atomicAdd(&g_cntB, 1u) == 31u) {
                atomicExch(&g_cntB, 0u);
                __threadfence();
                g_gen = gen + 1;
            }
        }
        while (g_gen == gen) __nanosleep(16);
        __threadfence();
    }
    __syncthreads();
}

// Relaxed end-of-step sync: only the 32 part0 blocks (ctx/h/argmax producers)
// arrive; everyone waits for those 32 only. Parts 1-3's record stores drain
// in the shadow of the next step's P1.
__device__ __forceinline__ void ctx_sync(int s, int part) {
    __threadfence();
    __syncthreads();
    if (threadIdx.x == 0) {
        if (part == 0) atomicAdd(&g_ctx_cnt, 1u);
        const unsigned tgt = 32u * (unsigned)(s + 1);
        while (*(volatile unsigned*)&g_ctx_cnt < tgt) __nanosleep(16);
        __threadfence();
    }
    __syncthreads();
}

__device__ __forceinline__ ull fma2(ull a, ull b, ull c) {
    ull d; asm("fma.rn.f32x2 %0,%1,%2,%3;" : "=l"(d) : "l"(a), "l"(b), "l"(c));
    return d;
}
__device__ __forceinline__ ull mul2(ull a, ull b) {
    ull d; asm("mul.rn.f32x2 %0,%1,%2;" : "=l"(d) : "l"(a), "l"(b));
    return d;
}
__device__ __forceinline__ ull pk2(float x, float y) {
    ull d; asm("mov.b64 %0,{%1,%2};" : "=l"(d) : "f"(x), "f"(y));
    return d;
}
__device__ __forceinline__ float2 unpk(ull v) {
    float2 r; asm("mov.b64 {%0,%1},%2;" : "=f"(r.x), "=f"(r.y) : "l"(v));
    return r;
}
__device__ __forceinline__ float wsum(float v) {
#pragma unroll
    for (int o = 16; o; o >>= 1) v += __shfl_xor_sync(0xffffffffu, v, o);
    return v;
}
__device__ __forceinline__ float wmax(float v) {
#pragma unroll
    for (int o = 16; o; o >>= 1) v = fmaxf(v, __shfl_xor_sync(0xffffffffu, v, o));
    return v;
}
__device__ __forceinline__ float fsig(float x) {
    return __fdividef(1.f, 1.f + __expf(-x));
}
__device__ __forceinline__ float ftanh(float x) {
    return 1.f - __fdividef(2.f, __expf(2.f * x) + 1.f);
}
__device__ __forceinline__ float ldcv(const float* p) {
    float v; asm("ld.global.cv.f32 %0,[%1];" : "=f"(v) : "l"(p));
    return v;
}
__device__ __forceinline__ int ldcvi(const int* p) {
    int v; asm("ld.global.cv.u32 %0,[%1];" : "=r"(v) : "l"(p));
    return v;
}
__device__ __forceinline__ float4 ldcv4(const float4* p) {
    float4 v;
    asm("ld.global.cv.v4.f32 {%0,%1,%2,%3},[%4];"
        : "=f"(v.x), "=f"(v.y), "=f"(v.z), "=f"(v.w) : "l"(p));
    return v;
}
// ---- TMA bulk-copy + mbarrier helpers ----
__device__ __forceinline__ unsigned smem_u32(const void* p) {
    unsigned r;
    asm("{ .reg .u64 t; cvta.to.shared.u64 t, %1; cvt.u32.u64 %0, t; }"
        : "=r"(r) : "l"(p));
    return r;
}
__device__ __forceinline__ void mbar_init(unsigned mbar, unsigned cnt) {
    asm volatile("mbarrier.init.shared.b64 [%0], %1;" :: "r"(mbar), "r"(cnt) : "memory");
}
__device__ __forceinline__ void mbar_expect(unsigned mbar, unsigned bytes) {
    asm volatile("mbarrier.arrive.expect_tx.shared.b64 _, [%0], %1;"
                 :: "r"(mbar), "r"(bytes) : "memory");
}
__device__ __forceinline__ void bulk_copy(unsigned dst, const void* src,
                                          unsigned bytes, unsigned mbar) {
    asm volatile("cp.async.bulk.shared::cluster.global.mbarrier::complete_tx::bytes "
                 "[%0], [%1], %2, [%3];"
                 :: "r"(dst), "l"(src), "r"(bytes), "r"(mbar) : "memory");
}
__device__ __forceinline__ void mbar_wait(unsigned mbar, unsigned parity) {
    asm volatile(
        "{\n\t.reg .pred P;\n\t"
        "WL%=:\n\t"
        "mbarrier.try_wait.parity.acquire.cta.shared::cta.b64 P, [%0], %1;\n\t"
        "@!P bra WL%=;\n\t}"
        :: "r"(mbar), "r"(parity) : "memory");
}
__device__ __forceinline__ void fence_async() {
    asm volatile("fence.proxy.async;" ::: "memory");
}

__global__ void __launch_bounds__(NTHR, 1) speller_kernel(
    const float* __restrict__ L,
    const float* __restrict__ W_ih,
    const float* __restrict__ W_hh,
    const float* __restrict__ b_ih,
    const float* __restrict__ b_hh,
    const float* __restrict__ W_out,
    const float* __restrict__ b_out,
    float* __restrict__ out_logp,
    float* __restrict__ out_attn)
{
    const int tid  = threadIdx.x;
    const int bid  = blockIdx.x;
    const int wid  = tid >> 5;
    const int lane = tid & 31;
    const int b    = bid >> 2, part = bid & 3;

    extern __shared__ float sm[];
    float* s_h      = sm + OFF_H;
    float* s_hc     = sm + OFF_HC;
    float* s_pm     = sm + OFF_PM;
    float* s_ps     = sm + OFF_PS;
    float* s_wgt    = sm + OFF_WGT;
    float* s_logits = sm + OFF_LOG;
    float* s_MS     = sm + OFF_MS;
    float* s_e      = sm + OFF_E;
    int*   s_idx    = (int*)(sm + OFF_IDX);
    float* s_one    = sm + OFF_ONE;
    float* s_bias   = sm + OFF_BIAS;

    const unsigned mb0   = smem_u32(sm + OFF_MB) + wid * 16;
    const unsigned mb1   = mb0 + 8;
    const unsigned slotB = smem_u32(sm) + wid * 8192;

    if (lane == 0) { mbar_init(mb0, 1); mbar_init(mb1, 1); fence_async(); }

    // ---------------- init ----------------
    for (int i = bid * NTHR + tid; i < Bq * Hh; i += NBLK * NTHR)
        (&g_c[0][0][0])[i] = 0.f;
    for (int i = bid * NTHR + tid; i < Bq * KK2; i += NBLK * NTHR) {
        int bb = i >> 10, k = i & 1023;
        g_xh2[bb][k] = (k < 512) ? L[(size_t)bb * Tt * Dd + k] : 0.f;
    }
    if (part == 0 && tid == 0) { g_bcnt[b] = 0; g_argmax[b] = 0; }
    if (bid == 0 && tid == 0) g_ctx_cnt = 0;   // replay-safe reset

    // stage W rows ONCE
    {
        float4* sW4 = (float4*)(sm + OFF_B);
        const float4* wi4 = (const float4*)W_ih + (size_t)(bid * 16) * 144;
        const float4* wh4 = (const float4*)W_hh + (size_t)(bid * 16) * 128;
        for (int idx = tid; idx < 16 * 128; idx += NTHR) {
            int jj = idx >> 7, c = idx & 127;
            sW4[jj * 257 + c]       = wi4[jj * 144 + 16 + c];
            sW4[jj * 257 + 128 + c] = wh4[idx];
        }
        for (int idx = tid; idx < 16 * 16; idx += NTHR) {
            int jj = idx >> 4, c = idx & 15;
            ((float4*)s_one)[jj * 16 + c] = wi4[jj * 144 + c];
        }
        if (tid < 16) {
            int j = bid * 16 + tid;
            s_bias[tid] = b_ih[j] + b_hh[j];
        }
    }
    grid_sync(b);

    const int gtype = bid >> 5;

    for (int s = 0; s < Ss; ++s) {
        const int crd = s & 1, cwr = crd ^ 1;

        // ========== P1: gates = Xh @ W^T — 16j x 32b warp tile, k-split 16 ==========
        {
            const float4* src = (const float4*)(&g_xh2[0][0]);
            float4* sX4 = (float4*)sm;
            for (int idx = tid; idx < 32 * 256; idx += NTHR) {
                int bb = idx >> 8, c = idx & 255;
                sX4[bb * 257 + c] = ldcv4(src + idx);
            }
            if (tid < 32) s_idx[tid] = ldcvi(&g_argmax[tid]);
            __syncthreads();

            const int jg2 = lane & 3, bg = lane >> 2;
            const float* wb0 = sm + OFF_B + jg2 * PIT + wid * 64;
            const float* xb0 = sm + bg * PIT + wid * 64;

            ull acc[4][4];
#pragma unroll
            for (int jj = 0; jj < 4; ++jj)
#pragma unroll
                for (int bb = 0; bb < 4; ++bb) acc[jj][bb] = 0ull;

#pragma unroll 4
            for (int kq = 0; kq < 16; ++kq) {
                const int off = kq * 4;
                ulonglong2 wv0 = *(const ulonglong2*)(wb0 + off);
                ulonglong2 wv1 = *(const ulonglong2*)(wb0 + 4 * PIT + off);
                ulonglong2 wv2 = *(const ulonglong2*)(wb0 + 8 * PIT + off);
                ulonglong2 wv3 = *(const ulonglong2*)(wb0 + 12 * PIT + off);
                ulonglong2 xv0 = *(const ulonglong2*)(xb0 + off);
                ulonglong2 xv1 = *(const ulonglong2*)(xb0 + 8 * PIT + off);
                ulonglong2 xv2 = *(const ulonglong2*)(xb0 + 16 * PIT + off);
                ulonglong2 xv3 = *(const ulonglong2*)(xb0 + 24 * PIT + off);
#define P1STEP(jj, wv) \
                acc[jj][0] = fma2(wv.x, xv0.x, acc[jj][0]); \
                acc[jj][0] = fma2(wv.y, xv0.y, acc[jj][0]); \
                acc[jj][1] = fma2(wv.x, xv1.x, acc[jj][1]); \
                acc[jj][1] = fma2(wv.y, xv1.y, acc[jj][1]); \
                acc[jj][2] = fma2(wv.x, xv2.x, acc[jj][2]); \
                acc[jj][2] = fma2(wv.y, xv2.y, acc[jj][2]); \
                acc[jj][3] = fma2(wv.x, xv3.x, acc[jj][3]); \
                acc[jj][3] = fma2(wv.y, xv3.y, acc[jj][3]);
                P1STEP(0, wv0)
                P1STEP(1, wv1)
                P1STEP(2, wv2)
                P1STEP(3, wv3)
#undef P1STEP
            }
            __syncthreads();
            float* sp = sm + wid * 640;
#pragma unroll
            for (int jj = 0; jj < 4; ++jj)
#pragma unroll
                for (int bb = 0; bb < 4; ++bb) {
                    float2 p = unpk(acc[jj][bb]);
                    const int j = jg2 + 4 * jj, bcol = bg + 8 * bb;
                    sp[j * 40 + bcol] = p.x + p.y;
                }
            __syncthreads();
            {
                float v = 0.f;
#pragma unroll
                for (int q = 0; q < 16; ++q)
                    v += sm[q * 640 + wid * 40 + lane];
                v += s_one[wid * 64 + s_idx[lane]] + s_bias[wid];
                float act = (gtype == 2) ? ftanh(v) : fsig(v);
                g_gates[lane][bid * 16 + wid] = act;
            }
        }
        grid_sync(b);

        // ========== P2: TMA-pipelined flash attention ==========
        {
            const char* Lb = (const char*)L + (size_t)b * Tt * Dd * 4;
            const int t0 = part * 256 + wid * 16;
            const char* srcBase = Lb + (size_t)t0 * 2048;

            if (lane == 0) {
                mbar_expect(mb0, 4096); bulk_copy(slotB,        srcBase,        4096, mb0);
                mbar_expect(mb1, 4096); bulk_copy(slotB + 4096, srcBase + 4096, 4096, mb1);
            }
            __syncwarp();

            {   // cell update with pre-activated gates
                const int k = tid;
                float iv = ldcv(&g_gates[b][k]);
                float fv = ldcv(&g_gates[b][512 + k]);
                float gv = ldcv(&g_gates[b][1024 + k]);
                float ov = ldcv(&g_gates[b][1536 + k]);
                float cp = ldcv(&g_c[crd][b][k]);
                float cn = fv * cp + iv * gv;
                float hn = ov * ftanh(cn);
                s_h[k] = hn;
                if (part == 0) { g_c[cwr][b][k] = cn; g_xh2[b][512 + k] = hn; }
            }
            __syncthreads();

            ull H[8];
            {
                const ulonglong2* h2 = (const ulonglong2*)s_h;
#pragma unroll
                for (int q = 0; q < 4; ++q) {
                    ulonglong2 t2 = h2[lane + (q << 5)];
                    H[2 * q] = t2.x; H[2 * q + 1] = t2.y;
                }
            }
            float m = -INFINITY, ss = 0.f;
            ull V[8];
#pragma unroll
            for (int q = 0; q < 8; ++q) V[q] = 0ull;

            const float* slotF = sm + wid * 2048;

#pragma unroll
            for (int st = 0; st < 8; ++st) {
                const unsigned mb = (st & 1) ? mb1 : mb0;
                mbar_wait(mb, (st >> 1) & 1);
                const ulonglong2* bufU2 =
                    (const ulonglong2*)(slotF + (st & 1) * 1024);

                ulonglong2 a0 = bufU2[lane];
                ulonglong2 a1 = bufU2[32 + lane];
                ulonglong2 a2 = bufU2[64 + lane];
                ulonglong2 a3 = bufU2[96 + lane];
                ulonglong2 b0 = bufU2[128 + lane];
                ulonglong2 b1 = bufU2[160 + lane];
                ulonglong2 b2 = bufU2[192 + lane];
                ulonglong2 b3 = bufU2[224 + lane];

                ull ea2 = mul2(a0.x, H[0]);
                ull eb2 = mul2(b0.x, H[0]);
                ea2 = fma2(a0.y, H[1], ea2); eb2 = fma2(b0.y, H[1], eb2);
                ea2 = fma2(a1.x, H[2], ea2); eb2 = fma2(b1.x, H[2], eb2);
                ea2 = fma2(a1.y, H[3], ea2); eb2 = fma2(b1.y, H[3], eb2);
                ea2 = fma2(a2.x, H[4], ea2); eb2 = fma2(b2.x, H[4], eb2);
                ea2 = fma2(a2.y, H[5], ea2); eb2 = fma2(b2.y, H[5], eb2);
                ea2 = fma2(a3.x, H[6], ea2); eb2 = fma2(b3.x, H[6], eb2);
                ea2 = fma2(a3.y, H[7], ea2); eb2 = fma2(b3.y, H[7], eb2);

                float2 fa = unpk(ea2), fb = unpk(eb2);
                float ea = fa.x + fa.y, eb = fb.x + fb.y;
#pragma unroll
                for (int o = 16; o; o >>= 1) {
                    ea += __shfl_xor_sync(0xffffffffu, ea, o);
                    eb += __shfl_xor_sync(0xffffffffu, eb, o);
                }
                if (lane == 0) {
                    s_e[wid * 16 + 2 * st]     = ea;
                    s_e[wid * 16 + 2 * st + 1] = eb;
                }

                float m_new = fmaxf(m, fmaxf(ea, eb));
                float wa = __expf(ea - m_new);
                float wb = __expf(eb - m_new);
                if (m_new > m) {
                    float sc = __expf(m - m_new);
                    ss = ss * sc;
                    ull sc2 = pk2(sc, sc);
#pragma unroll
                    for (int q = 0; q < 8; ++q) V[q] = mul2(V[q], sc2);
                    m = m_new;
                }
                ss += wa + wb;
                ull wa2 = pk2(wa, wa), wb2 = pk2(wb, wb);
                V[0] = fma2(a0.x, wa2, V[0]); V[0] = fma2(b0.x, wb2, V[0]);
                V[1] = fma2(a0.y, wa2, V[1]); V[1] = fma2(b0.y, wb2, V[1]);
                V[2] = fma2(a1.x, wa2, V[2]); V[2] = fma2(b1.x, wb2, V[2]);
                V[3] = fma2(a1.y, wa2, V[3]); V[3] = fma2(b1.y, wb2, V[3]);
                V[4] = fma2(a2.x, wa2, V[4]); V[4] = fma2(b2.x, wb2, V[4]);
                V[5] = fma2(a2.y, wa2, V[5]); V[5] = fma2(b2.y, wb2, V[5]);
                V[6] = fma2(a3.x, wa2, V[6]); V[6] = fma2(b3.x, wb2, V[6]);
                V[7] = fma2(a3.y, wa2, V[7]); V[7] = fma2(b3.y, wb2, V[7]);

                __syncwarp();
                if (lane == 0 && st + 2 < 8) {
                    mbar_expect(mb, 4096);
                    bulk_copy(slotB + (st & 1) * 4096,
                              srcBase + (size_t)(st + 2) * 4096, 4096, mb);
                }
            }

            __syncthreads();
            float* s_pv = sm;
            {
                ulonglong2* pv2 = (ulonglong2*)(s_pv + (wid << 9));
#pragma unroll
                for (int q = 0; q < 4; ++q) {
                    ulonglong2 t2; t2.x = V[2 * q]; t2.y = V[2 * q + 1];
                    pv2[lane + (q << 5)] = t2;
                }
                if (lane == 0) { s_pm[wid] = m; s_ps[wid] = ss; }
            }
            __syncthreads();
            if (wid == 0) {
                float mi = (lane < 16) ? s_pm[lane] : -INFINITY;
                float M = wmax(mi);
                float wg = (lane < 16) ? __expf(mi - M) : 0.f;
                if (lane < 16) s_wgt[lane] = wg;
                float sw = wsum((lane < 16) ? s_ps[lane] * wg : 0.f);
                if (lane == 0) { g_pm[b * 4 + part] = M; g_ps[b * 4 + part] = sw; }
            }
            if (part == 0 && tid >= 256) g_e0[b][tid - 256] = s_e[tid - 256];
            __syncthreads();
            {
                float acc = 0.f;
#pragma unroll
                for (int w = 0; w < 16; ++w)
                    acc += s_wgt[w] * s_pv[(w << 9) + tid];
                g_pvm[b][part][tid] = acc;
            }

            // ----- local sync among the 4 blocks of this batch -----
            __threadfence();
            __syncthreads();
            if (tid == 0) {
                atomicAdd(&g_bcnt[b], 1u);
                const unsigned tgt = 4u * (unsigned)(s + 1);
                while (((volatile unsigned*)g_bcnt)[b] < tgt) __nanosleep(16);
                __threadfence();
            }
            __syncthreads();

            // ----- merged P3: global merge, record, head (part0) -----
            if (wid == 0) {
                float mi = (lane < 4) ? ldcv(&g_pm[b * 4 + lane]) : -INFINITY;
                float M = wmax(mi);
                float wg = (lane < 4) ? __expf(mi - M) : 0.f;
                if (lane < 4) s_wgt[lane] = wg;
                float S = wsum((lane < 4) ? ldcv(&g_ps[b * 4 + lane]) * wg : 0.f);
                if (lane == 0) { s_MS[0] = M; s_MS[1] = __fdividef(1.f, S); }
            }
            __syncthreads();
            const float M = s_MS[0], invS = s_MS[1];
            float* rec = out_attn + ((size_t)s * Bq + b) * Tt;

            if (part != 0) {
                if (tid < 256)
                    rec[part * 256 + tid] = __expf(s_e[tid] - M) * invS;
                if (part == 1 && tid >= 256)
                    rec[tid - 256] = __expf(ldcv(&g_e0[b][tid - 256]) - M) * invS;
            } else {
                {
                    const int d = tid;
                    float acc = s_wgt[0] * ldcv(&g_pvm[b][0][d])
                              + s_wgt[1] * ldcv(&g_pvm[b][1][d])
                              + s_wgt[2] * ldcv(&g_pvm[b][2][d])
                              + s_wgt[3] * ldcv(&g_pvm[b][3][d]);
                    float ctx = acc * invS;
                    s_hc[Hh + d] = ctx;
                    g_xh2[b][d] = ctx;
                    s_hc[d] = s_h[d];
                }
                __syncthreads();
                {
                    ull C[16];
                    const ulonglong2* hc2 = (const ulonglong2*)s_hc;
#pragma unroll
                    for (int q = 0; q < 8; ++q) {
                        ulonglong2 t2 = hc2[lane + (q << 5)];
                        C[2 * q] = t2.x; C[2 * q + 1] = t2.y;
                    }
#pragma unroll
                    for (int rr = 0; rr < 4; ++rr) {
                        const int r = (wid << 2) | rr;
                        const ulonglong2* wr = (const ulonglong2*)(W_out + (size_t)r * 2 * Hh);
                        ull e2 = 0ull;
#pragma unroll
                        for (int q = 0; q < 8; ++q) {
                            ulonglong2 w2 = wr[lane + (q << 5)];
                            e2 = fma2(w2.x, C[2 * q], e2);
                            e2 = fma2(w2.y, C[2 * q + 1], e2);
                        }
                        float2 p = unpk(e2);
                        float v = wsum(p.x + p.y);
                        if (lane == 0) s_logits[r] = v + b_out[r];
                    }
                }
                __syncthreads();
                if (tid < 32) {
                    float z0 = s_logits[tid], z1 = s_logits[32 + tid];
                    float zm = wmax(fmaxf(z0, z1));
                    float es = wsum(__expf(z0 - zm) + __expf(z1 - zm));
                    float lse = zm + __logf(es);
                    float* lp = out_logp + ((size_t)s * Bq + b) * Vv;
                    lp[tid]      = z0 - lse;
                    lp[32 + tid] = z1 - lse;
                    float bv; int bi2;
                    if (z1 > z0) { bv = z1; bi2 = 32 + tid; } else { bv = z0; bi2 = tid; }
#pragma unroll
                    for (int o = 16; o; o >>= 1) {
                        float ov = __shfl_xor_sync(0xffffffffu, bv, o);
                        int   oi = __shfl_xor_sync(0xffffffffu, bi2, o);
                        if (ov > bv || (ov == bv && oi < bi2)) { bv = ov; bi2 = oi; }
                    }
                    if (tid == 0) g_argmax[b] = bi2;
                }
            }
        }
        ctx_sync(s, part);     // relaxed: wait only on the 32 ctx producers
    }
}

extern "C" void kernel_launch(void* const* d_in, const int* in_sizes, int n_in,
                              void* d_out, int out_size) {
    const float* L     = (const float*)d_in[0];
    const float* W_ih  = (const float*)d_in[1];
    const float* W_hh  = (const float*)d_in[2];
    const float* b_ih  = (const float*)d_in[3];
    const float* b_hh  = (const float*)d_in[4];
    const float* W_out = (const float*)d_in[5];
    const float* b_out = (const float*)d_in[6];
    float* out_logp = (float*)d_out;
    float* out_attn = (float*)d_out + (size_t)Ss * Bq * Vv;
    const int smem_bytes = SMEM_FLOATS * 4;
    cudaFuncSetAttribute(speller_kernel,
                         cudaFuncAttributeMaxDynamicSharedMemorySize, smem_bytes);
    speller_kernel<<<NBLK, NTHR, smem_bytes>>>(L, W_ih, W_hh, b_ih, b_hh,
                                               W_out, b_out, out_logp, out_attn);
}

// round 15
// speedup vs baseline: 1.1295x; 1.0155x over previous
#include <cuda_runtime.h>
#include <math.h>

#define Bq   32
#define Tt   1024
#define Dd   512
#define Hh   512
#define Vv   64
#define Ss   128
#define KK2  1024
#define G4   2048
#define NBLK 128
#define NTHR 512
#define PIT  1028

typedef unsigned long long ull;

// smem layout (float offsets)
#define OFF_A    0       /* 32896: P1 sX[32][1028]+sp; P2 TMA slots 16x2048 + s_pv */
#define OFF_B    32896   /* sW[16][1028] — staged ONCE */
#define OFF_ONE  49344
#define OFF_BIAS 50368
#define OFF_H    50384   /* 512  */
#define OFF_HC   50896   /* 1024 */
#define OFF_PM   51920
#define OFF_PS   51936
#define OFF_WGT  51952
#define OFF_LOG  51968
#define OFF_MS   52032
#define OFF_E    52036   /* 256 */
#define OFF_IDX  52292   /* 32 ints */
#define OFF_MB   52324   /* 68 floats: 16 warps x 2 mbarriers + 1 X-stage mbar */
#define SMEM_FLOATS 52392

// ---------------- device scratch ----------------
__device__ float g_xh2[Bq][KK2];
__device__ int   g_argmax[Bq];
__device__ float g_c[2][Bq][Hh];
__device__ float g_gates[Bq][G4];
__device__ float g_pm[Bq * 4];
__device__ float g_ps[Bq * 4];
__device__ float g_pvm[Bq][4][Dd];
__device__ float g_e0[Bq][256];
__device__ unsigned g_bcnt[Bq];

__device__ unsigned g_cntA[Bq];
__device__ unsigned g_cntB = 0;
__device__ volatile unsigned g_gen = 0;
__device__ unsigned g_ctx_cnt = 0;      // relaxed end-of-step: 32 part0 producers

__device__ __forceinline__ void grid_sync(int b) {
    __threadfence();
    __syncthreads();
    if (threadIdx.x == 0) {
        unsigned gen = g_gen;
        if (atomicAdd(&g_cntA[b], 1u) == 3u) {
            atomicExch(&g_cntA[b], 0u);
            if (atomicAdd(&g_cntB, 1u) == 31u) {
                atomicExch(&g_cntB, 0u);
                __threadfence();
                g_gen = gen + 1;
            }
        }
        while (g_gen == gen) __nanosleep(16);
        __threadfence();
    }
    __syncthreads();
}

// Relaxed end-of-step sync: only the 32 part0 blocks arrive.
__device__ __forceinline__ void ctx_sync(int s, int part) {
    __threadfence();
    __syncthreads();
    if (threadIdx.x == 0) {
        if (part == 0) atomicAdd(&g_ctx_cnt, 1u);
        const unsigned tgt = 32u * (unsigned)(s + 1);
        while (*(volatile unsigned*)&g_ctx_cnt < tgt) __nanosleep(16);
        __threadfence();
    }
    __syncthreads();
}

__device__ __forceinline__ ull fma2(ull a, ull b, ull c) {
    ull d; asm("fma.rn.f32x2 %0,%1,%2,%3;" : "=l"(d) : "l"(a), "l"(b), "l"(c));
    return d;
}
__device__ __forceinline__ ull mul2(ull a, ull b) {
    ull d; asm("mul.rn.f32x2 %0,%1,%2;" : "=l"(d) : "l"(a), "l"(b));
    return d;
}
__device__ __forceinline__ ull pk2(float x, float y) {
    ull d; asm("mov.b64 %0,{%1,%2};" : "=l"(d) : "f"(x), "f"(y));
    return d;
}
__device__ __forceinline__ float2 unpk(ull v) {
    float2 r; asm("mov.b64 {%0,%1},%2;" : "=f"(r.x), "=f"(r.y) : "l"(v));
    return r;
}
__device__ __forceinline__ float wsum(float v) {
#pragma unroll
    for (int o = 16; o; o >>= 1) v += __shfl_xor_sync(0xffffffffu, v, o);
    return v;
}
__device__ __forceinline__ float wmax(float v) {
#pragma unroll
    for (int o = 16; o; o >>= 1) v = fmaxf(v, __shfl_xor_sync(0xffffffffu, v, o));
    return v;
}
__device__ __forceinline__ float fsig(float x) {
    return __fdividef(1.f, 1.f + __expf(-x));
}
__device__ __forceinline__ float ftanh(float x) {
    return 1.f - __fdividef(2.f, __expf(2.f * x) + 1.f);
}
__device__ __forceinline__ float ldcv(const float* p) {
    float v; asm("ld.global.cv.f32 %0,[%1];" : "=f"(v) : "l"(p));
    return v;
}
__device__ __forceinline__ int ldcvi(const int* p) {
    int v; asm("ld.global.cv.u32 %0,[%1];" : "=r"(v) : "l"(p));
    return v;
}
// ---- TMA bulk-copy + mbarrier helpers ----
__device__ __forceinline__ unsigned smem_u32(const void* p) {
    unsigned r;
    asm("{ .reg .u64 t; cvta.to.shared.u64 t, %1; cvt.u32.u64 %0, t; }"
        : "=r"(r) : "l"(p));
    return r;
}
__device__ __forceinline__ void mbar_init(unsigned mbar, unsigned cnt) {
    asm volatile("mbarrier.init.shared.b64 [%0], %1;" :: "r"(mbar), "r"(cnt) : "memory");
}
__device__ __forceinline__ void mbar_expect(unsigned mbar, unsigned bytes) {
    asm volatile("mbarrier.arrive.expect_tx.shared.b64 _, [%0], %1;"
                 :: "r"(mbar), "r"(bytes) : "memory");
}
__device__ __forceinline__ void bulk_copy(unsigned dst, const void* src,
                                          unsigned bytes, unsigned mbar) {
    asm volatile("cp.async.bulk.shared::cluster.global.mbarrier::complete_tx::bytes "
                 "[%0], [%1], %2, [%3];"
                 :: "r"(dst), "l"(src), "r"(bytes), "r"(mbar) : "memory");
}
__device__ __forceinline__ void mbar_wait(unsigned mbar, unsigned parity) {
    asm volatile(
        "{\n\t.reg .pred P;\n\t"
        "WL%=:\n\t"
        "mbarrier.try_wait.parity.acquire.cta.shared::cta.b64 P, [%0], %1;\n\t"
        "@!P bra WL%=;\n\t}"
        :: "r"(mbar), "r"(parity) : "memory");
}
__device__ __forceinline__ void fence_async() {
    asm volatile("fence.proxy.async;" ::: "memory");
}

__global__ void __launch_bounds__(NTHR, 1) speller_kernel(
    const float* __restrict__ L,
    const float* __restrict__ W_ih,
    const float* __restrict__ W_hh,
    const float* __restrict__ b_ih,
    const float* __restrict__ b_hh,
    const float* __restrict__ W_out,
    const float* __restrict__ b_out,
    float* __restrict__ out_logp,
    float* __restrict__ out_attn)
{
    const int tid  = threadIdx.x;
    const int bid  = blockIdx.x;
    const int wid  = tid >> 5;
    const int lane = tid & 31;
    const int b    = bid >> 2, part = bid & 3;

    extern __shared__ float sm[];
    float* s_h      = sm + OFF_H;
    float* s_hc     = sm + OFF_HC;
    float* s_pm     = sm + OFF_PM;
    float* s_ps     = sm + OFF_PS;
    float* s_wgt    = sm + OFF_WGT;
    float* s_logits = sm + OFF_LOG;
    float* s_MS     = sm + OFF_MS;
    float* s_e      = sm + OFF_E;
    int*   s_idx    = (int*)(sm + OFF_IDX);
    float* s_one    = sm + OFF_ONE;
    float* s_bias   = sm + OFF_BIAS;

    const unsigned mb0   = smem_u32(sm + OFF_MB) + wid * 16;
    const unsigned mb1   = mb0 + 8;
    const unsigned mbX   = smem_u32(sm + OFF_MB) + 256;   // X-staging mbar
    const unsigned slotB = smem_u32(sm) + wid * 8192;
    const unsigned sXB   = smem_u32(sm);                  // base of sX region

    if (lane == 0) { mbar_init(mb0, 1); mbar_init(mb1, 1); }
    if (tid == 0)  { mbar_init(mbX, 1); }
    if (lane == 0 || tid == 0) fence_async();

    // ---------------- init ----------------
    for (int i = bid * NTHR + tid; i < Bq * Hh; i += NBLK * NTHR)
        (&g_c[0][0][0])[i] = 0.f;
    for (int i = bid * NTHR + tid; i < Bq * KK2; i += NBLK * NTHR) {
        int bb = i >> 10, k = i & 1023;
        g_xh2[bb][k] = (k < 512) ? L[(size_t)bb * Tt * Dd + k] : 0.f;
    }
    if (part == 0 && tid == 0) { g_bcnt[b] = 0; g_argmax[b] = 0; }
    if (bid == 0 && tid == 0) g_ctx_cnt = 0;

    // stage W rows ONCE
    {
        float4* sW4 = (float4*)(sm + OFF_B);
        const float4* wi4 = (const float4*)W_ih + (size_t)(bid * 16) * 144;
        const float4* wh4 = (const float4*)W_hh + (size_t)(bid * 16) * 128;
        for (int idx = tid; idx < 16 * 128; idx += NTHR) {
            int jj = idx >> 7, c = idx & 127;
            sW4[jj * 257 + c]       = wi4[jj * 144 + 16 + c];
            sW4[jj * 257 + 128 + c] = wh4[idx];
        }
        for (int idx = tid; idx < 16 * 16; idx += NTHR) {
            int jj = idx >> 4, c = idx & 15;
            ((float4*)s_one)[jj * 16 + c] = wi4[jj * 144 + c];
        }
        if (tid < 16) {
            int j = bid * 16 + tid;
            s_bias[tid] = b_ih[j] + b_hh[j];
        }
    }
    grid_sync(b);

    const int gtype = bid >> 5;

    for (int s = 0; s < Ss; ++s) {
        const int crd = s & 1, cwr = crd ^ 1;

        // ========== P1: TMA-staged X + gates GEMM (16j x 32b tile) ==========
        {
            // stage X[32][1024@pitch1028] via TMA: warp0, one 4KB row per lane
            if (wid == 0) {
                if (lane == 0) mbar_expect(mbX, 131072);
                __syncwarp();
                bulk_copy(sXB + (unsigned)lane * 4112, &g_xh2[lane][0], 4096, mbX);
            }
            if (tid < 32) s_idx[tid] = ldcvi(&g_argmax[tid]);
            __syncthreads();                 // s_idx visible; prior sm readers done
            mbar_wait(mbX, s & 1);           // X staged

            const int jg2 = lane & 3, bg = lane >> 2;
            const float* wb0 = sm + OFF_B + jg2 * PIT + wid * 64;
            const float* xb0 = sm + bg * PIT + wid * 64;

            ull acc[4][4];
#pragma unroll
            for (int jj = 0; jj < 4; ++jj)
#pragma unroll
                for (int bb = 0; bb < 4; ++bb) acc[jj][bb] = 0ull;

#pragma unroll 4
            for (int kq = 0; kq < 16; ++kq) {
                const int off = kq * 4;
                ulonglong2 wv0 = *(const ulonglong2*)(wb0 + off);
                ulonglong2 wv1 = *(const ulonglong2*)(wb0 + 4 * PIT + off);
                ulonglong2 wv2 = *(const ulonglong2*)(wb0 + 8 * PIT + off);
                ulonglong2 wv3 = *(const ulonglong2*)(wb0 + 12 * PIT + off);
                ulonglong2 xv0 = *(const ulonglong2*)(xb0 + off);
                ulonglong2 xv1 = *(const ulonglong2*)(xb0 + 8 * PIT + off);
                ulonglong2 xv2 = *(const ulonglong2*)(xb0 + 16 * PIT + off);
                ulonglong2 xv3 = *(const ulonglong2*)(xb0 + 24 * PIT + off);
#define P1STEP(jj, wv) \
                acc[jj][0] = fma2(wv.x, xv0.x, acc[jj][0]); \
                acc[jj][0] = fma2(wv.y, xv0.y, acc[jj][0]); \
                acc[jj][1] = fma2(wv.x, xv1.x, acc[jj][1]); \
                acc[jj][1] = fma2(wv.y, xv1.y, acc[jj][1]); \
                acc[jj][2] = fma2(wv.x, xv2.x, acc[jj][2]); \
                acc[jj][2] = fma2(wv.y, xv2.y, acc[jj][2]); \
                acc[jj][3] = fma2(wv.x, xv3.x, acc[jj][3]); \
                acc[jj][3] = fma2(wv.y, xv3.y, acc[jj][3]);
                P1STEP(0, wv0)
                P1STEP(1, wv1)
                P1STEP(2, wv2)
                P1STEP(3, wv3)
#undef P1STEP
            }
            __syncthreads();
            float* sp = sm + wid * 640;
#pragma unroll
            for (int jj = 0; jj < 4; ++jj)
#pragma unroll
                for (int bb = 0; bb < 4; ++bb) {
                    float2 p = unpk(acc[jj][bb]);
                    const int j = jg2 + 4 * jj, bcol = bg + 8 * bb;
                    sp[j * 40 + bcol] = p.x + p.y;
                }
            __syncthreads();
            {
                float v = 0.f;
#pragma unroll
                for (int q = 0; q < 16; ++q)
                    v += sm[q * 640 + wid * 40 + lane];
                v += s_one[wid * 64 + s_idx[lane]] + s_bias[wid];
                float act = (gtype == 2) ? ftanh(v) : fsig(v);
                g_gates[lane][bid * 16 + wid] = act;
            }
        }
        // prefetch c (stable since previous step) before waiting on gates
        const float cp = ldcv(&g_c[crd][b][tid]);
        grid_sync(b);

        // ========== P2: TMA-pipelined flash attention ==========
        {
            const char* Lb = (const char*)L + (size_t)b * Tt * Dd * 4;
            const int t0 = part * 256 + wid * 16;
            const char* srcBase = Lb + (size_t)t0 * 2048;

            if (lane == 0) {
                mbar_expect(mb0, 4096); bulk_copy(slotB,        srcBase,        4096, mb0);
                mbar_expect(mb1, 4096); bulk_copy(slotB + 4096, srcBase + 4096, 4096, mb1);
            }
            __syncwarp();

            {   // cell update with pre-activated gates (c prefetched)
                const int k = tid;
                float iv = ldcv(&g_gates[b][k]);
                float fv = ldcv(&g_gates[b][512 + k]);
                float gv = ldcv(&g_gates[b][1024 + k]);
                float ov = ldcv(&g_gates[b][1536 + k]);
                float cn = fv * cp + iv * gv;
                float hn = ov * ftanh(cn);
                s_h[k] = hn;
                if (part == 0) { g_c[cwr][b][k] = cn; g_xh2[b][512 + k] = hn; }
            }
            __syncthreads();

            ull H[8];
            {
                const ulonglong2* h2 = (const ulonglong2*)s_h;
#pragma unroll
                for (int q = 0; q < 4; ++q) {
                    ulonglong2 t2 = h2[lane + (q << 5)];
                    H[2 * q] = t2.x; H[2 * q + 1] = t2.y;
                }
            }
            float m = -INFINITY, ss = 0.f;
            ull V[8];
#pragma unroll
            for (int q = 0; q < 8; ++q) V[q] = 0ull;

            const float* slotF = sm + wid * 2048;

#pragma unroll
            for (int st = 0; st < 8; ++st) {
                const unsigned mb = (st & 1) ? mb1 : mb0;
                mbar_wait(mb, (st >> 1) & 1);
                const ulonglong2* bufU2 =
                    (const ulonglong2*)(slotF + (st & 1) * 1024);

                ulonglong2 a0 = bufU2[lane];
                ulonglong2 a1 = bufU2[32 + lane];
                ulonglong2 a2 = bufU2[64 + lane];
                ulonglong2 a3 = bufU2[96 + lane];
                ulonglong2 b0 = bufU2[128 + lane];
                ulonglong2 b1 = bufU2[160 + lane];
                ulonglong2 b2 = bufU2[192 + lane];
                ulonglong2 b3 = bufU2[224 + lane];

                ull ea2 = mul2(a0.x, H[0]);
                ull eb2 = mul2(b0.x, H[0]);
                ea2 = fma2(a0.y, H[1], ea2); eb2 = fma2(b0.y, H[1], eb2);
                ea2 = fma2(a1.x, H[2], ea2); eb2 = fma2(b1.x, H[2], eb2);
                ea2 = fma2(a1.y, H[3], ea2); eb2 = fma2(b1.y, H[3], eb2);
                ea2 = fma2(a2.x, H[4], ea2); eb2 = fma2(b2.x, H[4], eb2);
                ea2 = fma2(a2.y, H[5], ea2); eb2 = fma2(b2.y, H[5], eb2);
                ea2 = fma2(a3.x, H[6], ea2); eb2 = fma2(b3.x, H[6], eb2);
                ea2 = fma2(a3.y, H[7], ea2); eb2 = fma2(b3.y, H[7], eb2);

                float2 fa = unpk(ea2), fb = unpk(eb2);
                float ea = fa.x + fa.y, eb = fb.x + fb.y;
#pragma unroll
                for (int o = 16; o; o >>= 1) {
                    ea += __shfl_xor_sync(0xffffffffu, ea, o);
                    eb += __shfl_xor_sync(0xffffffffu, eb, o);
                }
                if (lane == 0) {
                    s_e[wid * 16 + 2 * st]     = ea;
                    s_e[wid * 16 + 2 * st + 1] = eb;
                }

                float m_new = fmaxf(m, fmaxf(ea, eb));
                float wa = __expf(ea - m_new);
                float wb = __expf(eb - m_new);
                if (m_new > m) {
                    float sc = __expf(m - m_new);
                    ss = ss * sc;
                    ull sc2 = pk2(sc, sc);
#pragma unroll
                    for (int q = 0; q < 8; ++q) V[q] = mul2(V[q], sc2);
                    m = m_new;
                }
                ss += wa + wb;
                ull wa2 = pk2(wa, wa), wb2 = pk2(wb, wb);
                V[0] = fma2(a0.x, wa2, V[0]); V[0] = fma2(b0.x, wb2, V[0]);
                V[1] = fma2(a0.y, wa2, V[1]); V[1] = fma2(b0.y, wb2, V[1]);
                V[2] = fma2(a1.x, wa2, V[2]); V[2] = fma2(b1.x, wb2, V[2]);
                V[3] = fma2(a1.y, wa2, V[3]); V[3] = fma2(b1.y, wb2, V[3]);
                V[4] = fma2(a2.x, wa2, V[4]); V[4] = fma2(b2.x, wb2, V[4]);
                V[5] = fma2(a2.y, wa2, V[5]); V[5] = fma2(b2.y, wb2, V[5]);
                V[6] = fma2(a3.x, wa2, V[6]); V[6] = fma2(b3.x, wb2, V[6]);
                V[7] = fma2(a3.y, wa2, V[7]); V[7] = fma2(b3.y, wb2, V[7]);

                __syncwarp();
                if (lane == 0 && st + 2 < 8) {
                    mbar_expect(mb, 4096);
                    bulk_copy(slotB + (st & 1) * 4096,
                              srcBase + (size_t)(st + 2) * 4096, 4096, mb);
                }
            }

            __syncthreads();
            float* s_pv = sm;
            {
                ulonglong2* pv2 = (ulonglong2*)(s_pv + (wid << 9));
#pragma unroll
                for (int q = 0; q < 4; ++q) {
                    ulonglong2 t2; t2.x = V[2 * q]; t2.y = V[2 * q + 1];
                    pv2[lane + (q << 5)] = t2;
                }
                if (lane == 0) { s_pm[wid] = m; s_ps[wid] = ss; }
            }
            __syncthreads();
            if (wid == 0) {
                float mi = (lane < 16) ? s_pm[lane] : -INFINITY;
                float M = wmax(mi);
                float wg = (lane < 16) ? __expf(mi - M) : 0.f;
                if (lane < 16) s_wgt[lane] = wg;
                float sw = wsum((lane < 16) ? s_ps[lane] * wg : 0.f);
                if (lane == 0) { g_pm[b * 4 + part] = M; g_ps[b * 4 + part] = sw; }
            }
            if (part == 0 && tid >= 256) g_e0[b][tid - 256] = s_e[tid - 256];
            __syncthreads();
            {
                float acc = 0.f;
#pragma unroll
                for (int w = 0; w < 16; ++w)
                    acc += s_wgt[w] * s_pv[(w << 9) + tid];
                g_pvm[b][part][tid] = acc;
            }

            // ----- local sync among the 4 blocks of this batch -----
            __threadfence();
            __syncthreads();
            if (tid == 0) {
                atomicAdd(&g_bcnt[b], 1u);
                const unsigned tgt = 4u * (unsigned)(s + 1);
                while (((volatile unsigned*)g_bcnt)[b] < tgt) __nanosleep(16);
                __threadfence();
            }
            __syncthreads();

            // ----- merged P3: global merge, record, head (part0) -----
            if (wid == 0) {
                float mi = (lane < 4) ? ldcv(&g_pm[b * 4 + lane]) : -INFINITY;
                float M = wmax(mi);
                float wg = (lane < 4) ? __expf(mi - M) : 0.f;
                if (lane < 4) s_wgt[lane] = wg;
                float S = wsum((lane < 4) ? ldcv(&g_ps[b * 4 + lane]) * wg : 0.f);
                if (lane == 0) { s_MS[0] = M; s_MS[1] = __fdividef(1.f, S); }
            }
            __syncthreads();
            const float M = s_MS[0], invS = s_MS[1];
            float* rec = out_attn + ((size_t)s * Bq + b) * Tt;

            if (part != 0) {
                if (tid < 256)
                    rec[part * 256 + tid] = __expf(s_e[tid] - M) * invS;
                if (part == 1 && tid >= 256)
                    rec[tid - 256] = __expf(ldcv(&g_e0[b][tid - 256]) - M) * invS;
            } else {
                {
                    const int d = tid;
                    float acc = s_wgt[0] * ldcv(&g_pvm[b][0][d])
                              + s_wgt[1] * ldcv(&g_pvm[b][1][d])
                              + s_wgt[2] * ldcv(&g_pvm[b][2][d])
                              + s_wgt[3] * ldcv(&g_pvm[b][3][d]);
                    float ctx = acc * invS;
                    s_hc[Hh + d] = ctx;
                    g_xh2[b][d] = ctx;
                    s_hc[d] = s_h[d];
                }
                __syncthreads();
                {
                    ull C[16];
                    const ulonglong2* hc2 = (const ulonglong2*)s_hc;
#pragma unroll
                    for (int q = 0; q < 8; ++q) {
                        ulonglong2 t2 = hc2[lane + (q << 5)];
                        C[2 * q] = t2.x; C[2 * q + 1] = t2.y;
                    }
#pragma unroll
                    for (int rr = 0; rr < 4; ++rr) {
                        const int r = (wid << 2) | rr;
                        const ulonglong2* wr = (const ulonglong2*)(W_out + (size_t)r * 2 * Hh);
                        ull e2 = 0ull;
#pragma unroll
                        for (int q = 0; q < 8; ++q) {
                            ulonglong2 w2 = wr[lane + (q << 5)];
                            e2 = fma2(w2.x, C[2 * q], e2);
                            e2 = fma2(w2.y, C[2 * q + 1], e2);
                        }
                        float2 p = unpk(e2);
                        float v = wsum(p.x + p.y);
                        if (lane == 0) s_logits[r] = v + b_out[r];
                    }
                }
                __syncthreads();
                if (tid < 32) {
                    float z0 = s_logits[tid], z1 = s_logits[32 + tid];
                    float zm = wmax(fmaxf(z0, z1));
                    float es = wsum(__expf(z0 - zm) + __expf(z1 - zm));
                    float lse = zm + __logf(es);
                    float* lp = out_logp + ((size_t)s * Bq + b) * Vv;
                    lp[tid]      = z0 - lse;
                    lp[32 + tid] = z1 - lse;
                    float bv; int bi2;
                    if (z1 > z0) { bv = z1; bi2 = 32 + tid; } else { bv = z0; bi2 = tid; }
#pragma unroll
                    for (int o = 16; o; o >>= 1) {
                        float ov = __shfl_xor_sync(0xffffffffu, bv, o);
                        int   oi = __shfl_xor_sync(0xffffffffu, bi2, o);
                        if (ov > bv || (ov == bv && oi < bi2)) { bv = ov; bi2 = oi; }
                    }
                    if (tid == 0) g_argmax[b] = bi2;
                }
            }
        }
        ctx_sync(s, part);     // relaxed: wait only on the 32 ctx producers
    }
}

extern "C" void kernel_launch(void* const* d_in, const int* in_sizes, int n_in,
                              void* d_out, int out_size) {
    const float* L     = (const float*)d_in[0];
    const float* W_ih  = (const float*)d_in[1];
    const float* W_hh  = (const float*)d_in[2];
    const float* b_ih  = (const float*)d_in[3];
    const float* b_hh  = (const float*)d_in[4];
    const float* W_out = (const float*)d_in[5];
    const float* b_out = (const float*)d_in[6];
    float* out_logp = (float*)d_out;
    float* out_attn = (float*)d_out + (size_t)Ss * Bq * Vv;
    const int smem_bytes = SMEM_FLOATS * 4;
    cudaFuncSetAttribute(speller_kernel,
                         cudaFuncAttributeMaxDynamicSharedMemorySize, smem_bytes);
    speller_kernel<<<NBLK, NTHR, smem_bytes>>>(L, W_ih, W_hh, b_ih, b_hh,
                                               W_out, b_out, out_logp, out_attn);
}

// round 16
// speedup vs baseline: 1.1426x; 1.0117x over previous
#include <cuda_runtime.h>
#include <math.h>

#define Bq   32
#define Tt   1024
#define Dd   512
#define Hh   512
#define Vv   64
#define Ss   128
#define KK2  1024
#define G4   2048
#define NBLK 128
#define NTHR 512
#define PIT  1028

typedef unsigned long long ull;

// smem layout (float offsets)
#define OFF_A    0       /* 32896: P1 sX[32][1028]+sp; P2 TMA slots 16x2048 + s_pv */
#define OFF_B    32896   /* sW[16][1028] — staged ONCE */
#define OFF_ONE  49344
#define OFF_BIAS 50368
#define OFF_H    50384   /* 512  */
#define OFF_HC   50896   /* 1024 */
#define OFF_PM   51920
#define OFF_PS   51936
#define OFF_WGT  51952
#define OFF_LOG  51968
#define OFF_MS   52032
#define OFF_E    52036   /* 256 */
#define OFF_IDX  52292   /* 32 ints */
#define OFF_MB   52324   /* 68 floats: 16 warps x 2 mbarriers + 1 X-stage mbar */
#define SMEM_FLOATS 52392

// ---------------- device scratch ----------------
__device__ float g_xh2[Bq][KK2];
__device__ int   g_argmax[Bq];
__device__ float g_c[2][Bq][Hh];
__device__ float g_gates[Bq][G4];
__device__ float g_pm[Bq * 4];
__device__ float g_ps[Bq * 4];
__device__ float g_pvm[Bq][4][Dd];
__device__ float g_e0[Bq][256];
__device__ unsigned g_bcnt[Bq];

__device__ unsigned g_cntA[Bq];
__device__ unsigned g_cntB = 0;
__device__ volatile unsigned g_gen = 0;
__device__ unsigned g_ctx_cnt = 0;      // relaxed end-of-step: 32 part0 producers

__device__ __forceinline__ void grid_sync(int b) {
    __threadfence();
    __syncthreads();
    if (threadIdx.x == 0) {
        unsigned gen = g_gen;
        if (atomicAdd(&g_cntA[b], 1u) == 3u) {
            atomicExch(&g_cntA[b], 0u);
            if (atomicAdd(&g_cntB, 1u) == 31u) {
                atomicExch(&g_cntB, 0u);
                __threadfence();
                g_gen = gen + 1;
            }
        }
        while (g_gen == gen) __nanosleep(16);
        __threadfence();
    }
    __syncthreads();
}

// Relaxed end-of-step sync: only the 32 part0 blocks arrive.
__device__ __forceinline__ void ctx_sync(int s, int part) {
    __threadfence();
    __syncthreads();
    if (threadIdx.x == 0) {
        if (part == 0) atomicAdd(&g_ctx_cnt, 1u);
        const unsigned tgt = 32u * (unsigned)(s + 1);
        while (*(volatile unsigned*)&g_ctx_cnt < tgt) __nanosleep(16);
        __threadfence();
    }
    __syncthreads();
}

__device__ __forceinline__ ull fma2(ull a, ull b, ull c) {
    ull d; asm("fma.rn.f32x2 %0,%1,%2,%3;" : "=l"(d) : "l"(a), "l"(b), "l"(c));
    return d;
}
__device__ __forceinline__ ull mul2(ull a, ull b) {
    ull d; asm("mul.rn.f32x2 %0,%1,%2;" : "=l"(d) : "l"(a), "l"(b));
    return d;
}
__device__ __forceinline__ ull add2(ull a, ull b) {
    ull d; asm("add.rn.f32x2 %0,%1,%2;" : "=l"(d) : "l"(a), "l"(b));
    return d;
}
__device__ __forceinline__ ull pk2(float x, float y) {
    ull d; asm("mov.b64 %0,{%1,%2};" : "=l"(d) : "f"(x), "f"(y));
    return d;
}
__device__ __forceinline__ float2 unpk(ull v) {
    float2 r; asm("mov.b64 {%0,%1},%2;" : "=f"(r.x), "=f"(r.y) : "l"(v));
    return r;
}
__device__ __forceinline__ float wsum(float v) {
#pragma unroll
    for (int o = 16; o; o >>= 1) v += __shfl_xor_sync(0xffffffffu, v, o);
    return v;
}
__device__ __forceinline__ float wmax(float v) {
#pragma unroll
    for (int o = 16; o; o >>= 1) v = fmaxf(v, __shfl_xor_sync(0xffffffffu, v, o));
    return v;
}
__device__ __forceinline__ float fsig(float x) {
    return __fdividef(1.f, 1.f + __expf(-x));
}
__device__ __forceinline__ float ftanh(float x) {
    return 1.f - __fdividef(2.f, __expf(2.f * x) + 1.f);
}
__device__ __forceinline__ float ldcv(const float* p) {
    float v; asm("ld.global.cv.f32 %0,[%1];" : "=f"(v) : "l"(p));
    return v;
}
__device__ __forceinline__ int ldcvi(const int* p) {
    int v; asm("ld.global.cv.u32 %0,[%1];" : "=r"(v) : "l"(p));
    return v;
}
// ---- TMA bulk-copy + mbarrier helpers ----
__device__ __forceinline__ unsigned smem_u32(const void* p) {
    unsigned r;
    asm("{ .reg .u64 t; cvta.to.shared.u64 t, %1; cvt.u32.u64 %0, t; }"
        : "=r"(r) : "l"(p));
    return r;
}
__device__ __forceinline__ void mbar_init(unsigned mbar, unsigned cnt) {
    asm volatile("mbarrier.init.shared.b64 [%0], %1;" :: "r"(mbar), "r"(cnt) : "memory");
}
__device__ __forceinline__ void mbar_expect(unsigned mbar, unsigned bytes) {
    asm volatile("mbarrier.arrive.expect_tx.shared.b64 _, [%0], %1;"
                 :: "r"(mbar), "r"(bytes) : "memory");
}
__device__ __forceinline__ void bulk_copy(unsigned dst, const void* src,
                                          unsigned bytes, unsigned mbar) {
    asm volatile("cp.async.bulk.shared::cluster.global.mbarrier::complete_tx::bytes "
                 "[%0], [%1], %2, [%3];"
                 :: "r"(dst), "l"(src), "r"(bytes), "r"(mbar) : "memory");
}
__device__ __forceinline__ void mbar_wait(unsigned mbar, unsigned parity) {
    asm volatile(
        "{\n\t.reg .pred P;\n\t"
        "WL%=:\n\t"
        "mbarrier.try_wait.parity.acquire.cta.shared::cta.b64 P, [%0], %1;\n\t"
        "@!P bra WL%=;\n\t}"
        :: "r"(mbar), "r"(parity) : "memory");
}
__device__ __forceinline__ void fence_async() {
    asm volatile("fence.proxy.async;" ::: "memory");
}

__global__ void __launch_bounds__(NTHR, 1) speller_kernel(
    const float* __restrict__ L,
    const float* __restrict__ W_ih,
    const float* __restrict__ W_hh,
    const float* __restrict__ b_ih,
    const float* __restrict__ b_hh,
    const float* __restrict__ W_out,
    const float* __restrict__ b_out,
    float* __restrict__ out_logp,
    float* __restrict__ out_attn)
{
    const int tid  = threadIdx.x;
    const int bid  = blockIdx.x;
    const int wid  = tid >> 5;
    const int lane = tid & 31;
    const int b    = bid >> 2, part = bid & 3;

    extern __shared__ float sm[];
    float* s_h      = sm + OFF_H;
    float* s_hc     = sm + OFF_HC;
    float* s_pm     = sm + OFF_PM;
    float* s_ps     = sm + OFF_PS;
    float* s_wgt    = sm + OFF_WGT;
    float* s_logits = sm + OFF_LOG;
    float* s_MS     = sm + OFF_MS;
    float* s_e      = sm + OFF_E;
    int*   s_idx    = (int*)(sm + OFF_IDX);
    float* s_one    = sm + OFF_ONE;
    float* s_bias   = sm + OFF_BIAS;

    const unsigned mb0   = smem_u32(sm + OFF_MB) + wid * 16;
    const unsigned mb1   = mb0 + 8;
    const unsigned mbX   = smem_u32(sm + OFF_MB) + 256;   // X-staging mbar
    const unsigned slotB = smem_u32(sm) + wid * 8192;
    const unsigned sXB   = smem_u32(sm);                  // base of sX region

    if (lane == 0) { mbar_init(mb0, 1); mbar_init(mb1, 1); }
    if (tid == 0)  { mbar_init(mbX, 1); }
    if (lane == 0 || tid == 0) fence_async();

    // ---------------- init ----------------
    for (int i = bid * NTHR + tid; i < Bq * Hh; i += NBLK * NTHR)
        (&g_c[0][0][0])[i] = 0.f;
    for (int i = bid * NTHR + tid; i < Bq * KK2; i += NBLK * NTHR) {
        int bb = i >> 10, k = i & 1023;
        g_xh2[bb][k] = (k < 512) ? L[(size_t)bb * Tt * Dd + k] : 0.f;
    }
    if (part == 0 && tid == 0) { g_bcnt[b] = 0; g_argmax[b] = 0; }
    if (bid == 0 && tid == 0) g_ctx_cnt = 0;

    // stage W rows ONCE
    {
        float4* sW4 = (float4*)(sm + OFF_B);
        const float4* wi4 = (const float4*)W_ih + (size_t)(bid * 16) * 144;
        const float4* wh4 = (const float4*)W_hh + (size_t)(bid * 16) * 128;
        for (int idx = tid; idx < 16 * 128; idx += NTHR) {
            int jj = idx >> 7, c = idx & 127;
            sW4[jj * 257 + c]       = wi4[jj * 144 + 16 + c];
            sW4[jj * 257 + 128 + c] = wh4[idx];
        }
        for (int idx = tid; idx < 16 * 16; idx += NTHR) {
            int jj = idx >> 4, c = idx & 15;
            ((float4*)s_one)[jj * 16 + c] = wi4[jj * 144 + c];
        }
        if (tid < 16) {
            int j = bid * 16 + tid;
            s_bias[tid] = b_ih[j] + b_hh[j];
        }
    }
    grid_sync(b);

    const int gtype = bid >> 5;
    const char* Lb = (const char*)L + (size_t)b * Tt * Dd * 4;
    const int t0 = part * 256 + wid * 16;
    const char* srcBase = Lb + (size_t)t0 * 2048;   // loop-invariant

    for (int s = 0; s < Ss; ++s) {
        const int crd = s & 1, cwr = crd ^ 1;

        // ========== P1: TMA-staged X + gates GEMM (16j x 32b tile) ==========
        {
            // stage X[32][1024@pitch1028] via TMA: warp0, one 4KB row per lane
            if (wid == 0) {
                if (lane == 0) mbar_expect(mbX, 131072);
                __syncwarp();
                bulk_copy(sXB + (unsigned)lane * 4112, &g_xh2[lane][0], 4096, mbX);
            }
            if (tid < 32) s_idx[tid] = ldcvi(&g_argmax[tid]);
            __syncthreads();                 // s_idx visible; prior sm readers done
            mbar_wait(mbX, s & 1);           // X staged

            const int jg2 = lane & 3, bg = lane >> 2;
            const float* wb0 = sm + OFF_B + jg2 * PIT + wid * 64;
            const float* xb0 = sm + bg * PIT + wid * 64;

            ull acc[4][4];
#pragma unroll
            for (int jj = 0; jj < 4; ++jj)
#pragma unroll
                for (int bb = 0; bb < 4; ++bb) acc[jj][bb] = 0ull;

#pragma unroll 4
            for (int kq = 0; kq < 16; ++kq) {
                const int off = kq * 4;
                ulonglong2 wv0 = *(const ulonglong2*)(wb0 + off);
                ulonglong2 wv1 = *(const ulonglong2*)(wb0 + 4 * PIT + off);
                ulonglong2 wv2 = *(const ulonglong2*)(wb0 + 8 * PIT + off);
                ulonglong2 wv3 = *(const ulonglong2*)(wb0 + 12 * PIT + off);
                ulonglong2 xv0 = *(const ulonglong2*)(xb0 + off);
                ulonglong2 xv1 = *(const ulonglong2*)(xb0 + 8 * PIT + off);
                ulonglong2 xv2 = *(const ulonglong2*)(xb0 + 16 * PIT + off);
                ulonglong2 xv3 = *(const ulonglong2*)(xb0 + 24 * PIT + off);
#define P1STEP(jj, wv) \
                acc[jj][0] = fma2(wv.x, xv0.x, acc[jj][0]); \
                acc[jj][0] = fma2(wv.y, xv0.y, acc[jj][0]); \
                acc[jj][1] = fma2(wv.x, xv1.x, acc[jj][1]); \
                acc[jj][1] = fma2(wv.y, xv1.y, acc[jj][1]); \
                acc[jj][2] = fma2(wv.x, xv2.x, acc[jj][2]); \
                acc[jj][2] = fma2(wv.y, xv2.y, acc[jj][2]); \
                acc[jj][3] = fma2(wv.x, xv3.x, acc[jj][3]); \
                acc[jj][3] = fma2(wv.y, xv3.y, acc[jj][3]);
                P1STEP(0, wv0)
                P1STEP(1, wv1)
                P1STEP(2, wv2)
                P1STEP(3, wv3)
#undef P1STEP
            }
            __syncthreads();
            float* sp = sm + wid * 640;
#pragma unroll
            for (int jj = 0; jj < 4; ++jj)
#pragma unroll
                for (int bb = 0; bb < 4; ++bb) {
                    float2 p = unpk(acc[jj][bb]);
                    const int j = jg2 + 4 * jj, bcol = bg + 8 * bb;
                    sp[j * 40 + bcol] = p.x + p.y;
                }
            __syncthreads();
            {
                float v = 0.f;
#pragma unroll
                for (int q = 0; q < 16; ++q)
                    v += sm[q * 640 + wid * 40 + lane];
                v += s_one[wid * 64 + s_idx[lane]] + s_bias[wid];
                float act = (gtype == 2) ? ftanh(v) : fsig(v);
                g_gates[lane][bid * 16 + wid] = act;
            }
        }
        // region A fully read; prime P2's first two TMA stages so the
        // transfer latency lands under the grid sync below.
        __syncthreads();
        if (lane == 0) {
            mbar_expect(mb0, 4096); bulk_copy(slotB,        srcBase,        4096, mb0);
            mbar_expect(mb1, 4096); bulk_copy(slotB + 4096, srcBase + 4096, 4096, mb1);
        }
        // prefetch c (stable since previous step) before waiting on gates
        const float cp = ldcv(&g_c[crd][b][tid]);
        grid_sync(b);

        // ========== P2: TMA-pipelined flash attention ==========
        {
            {   // cell update with pre-activated gates (c prefetched)
                const int k = tid;
                float iv = ldcv(&g_gates[b][k]);
                float fv = ldcv(&g_gates[b][512 + k]);
                float gv = ldcv(&g_gates[b][1024 + k]);
                float ov = ldcv(&g_gates[b][1536 + k]);
                float cn = fv * cp + iv * gv;
                float hn = ov * ftanh(cn);
                s_h[k] = hn;
                if (part == 0) { g_c[cwr][b][k] = cn; g_xh2[b][512 + k] = hn; }
            }
            __syncthreads();

            ull H[8];
            {
                const ulonglong2* h2 = (const ulonglong2*)s_h;
#pragma unroll
                for (int q = 0; q < 4; ++q) {
                    ulonglong2 t2 = h2[lane + (q << 5)];
                    H[2 * q] = t2.x; H[2 * q + 1] = t2.y;
                }
            }
            float m = -INFINITY, ss = 0.f;
            ull V[8];
#pragma unroll
            for (int q = 0; q < 8; ++q) V[q] = 0ull;

            const float* slotF = sm + wid * 2048;

#pragma unroll
            for (int st = 0; st < 8; ++st) {
                const unsigned mb = (st & 1) ? mb1 : mb0;
                mbar_wait(mb, (st >> 1) & 1);
                const ulonglong2* bufU2 =
                    (const ulonglong2*)(slotF + (st & 1) * 1024);

                ulonglong2 a0 = bufU2[lane];
                ulonglong2 a1 = bufU2[32 + lane];
                ulonglong2 a2 = bufU2[64 + lane];
                ulonglong2 a3 = bufU2[96 + lane];
                ulonglong2 b0 = bufU2[128 + lane];
                ulonglong2 b1 = bufU2[160 + lane];
                ulonglong2 b2 = bufU2[192 + lane];
                ulonglong2 b3 = bufU2[224 + lane];

                ull ea2 = mul2(a0.x, H[0]);
                ull eb2 = mul2(b0.x, H[0]);
                ea2 = fma2(a0.y, H[1], ea2); eb2 = fma2(b0.y, H[1], eb2);
                ea2 = fma2(a1.x, H[2], ea2); eb2 = fma2(b1.x, H[2], eb2);
                ea2 = fma2(a1.y, H[3], ea2); eb2 = fma2(b1.y, H[3], eb2);
                ea2 = fma2(a2.x, H[4], ea2); eb2 = fma2(b2.x, H[4], eb2);
                ea2 = fma2(a2.y, H[5], ea2); eb2 = fma2(b2.y, H[5], eb2);
                ea2 = fma2(a3.x, H[6], ea2); eb2 = fma2(b3.x, H[6], eb2);
                ea2 = fma2(a3.y, H[7], ea2); eb2 = fma2(b3.y, H[7], eb2);

                float2 fa = unpk(ea2), fb = unpk(eb2);
                float ea = fa.x + fa.y, eb = fb.x + fb.y;
#pragma unroll
                for (int o = 16; o; o >>= 1) {
                    ea += __shfl_xor_sync(0xffffffffu, ea, o);
                    eb += __shfl_xor_sync(0xffffffffu, eb, o);
                }
                if (lane == 0) {
                    s_e[wid * 16 + 2 * st]     = ea;
                    s_e[wid * 16 + 2 * st + 1] = eb;
                }

                float m_new = fmaxf(m, fmaxf(ea, eb));
                float wa = __expf(ea - m_new);
                float wb = __expf(eb - m_new);
                if (m_new > m) {
                    float sc = __expf(m - m_new);
                    ss = ss * sc;
                    ull sc2 = pk2(sc, sc);
#pragma unroll
                    for (int q = 0; q < 8; ++q) V[q] = mul2(V[q], sc2);
                    m = m_new;
                }
                ss += wa + wb;
                ull wa2 = pk2(wa, wa), wb2 = pk2(wb, wb);
                V[0] = fma2(a0.x, wa2, V[0]); V[0] = fma2(b0.x, wb2, V[0]);
                V[1] = fma2(a0.y, wa2, V[1]); V[1] = fma2(b0.y, wb2, V[1]);
                V[2] = fma2(a1.x, wa2, V[2]); V[2] = fma2(b1.x, wb2, V[2]);
                V[3] = fma2(a1.y, wa2, V[3]); V[3] = fma2(b1.y, wb2, V[3]);
                V[4] = fma2(a2.x, wa2, V[4]); V[4] = fma2(b2.x, wb2, V[4]);
                V[5] = fma2(a2.y, wa2, V[5]); V[5] = fma2(b2.y, wb2, V[5]);
                V[6] = fma2(a3.x, wa2, V[6]); V[6] = fma2(b3.x, wb2, V[6]);
                V[7] = fma2(a3.y, wa2, V[7]); V[7] = fma2(b3.y, wb2, V[7]);

                __syncwarp();
                if (lane == 0 && st + 2 < 8) {
                    mbar_expect(mb, 4096);
                    bulk_copy(slotB + (st & 1) * 4096,
                              srcBase + (size_t)(st + 2) * 4096, 4096, mb);
                }
            }

            __syncthreads();
            float* s_pv = sm;
            {
                ulonglong2* pv2 = (ulonglong2*)(s_pv + (wid << 9));
#pragma unroll
                for (int q = 0; q < 4; ++q) {
                    ulonglong2 t2; t2.x = V[2 * q]; t2.y = V[2 * q + 1];
                    pv2[lane + (q << 5)] = t2;
                }
                if (lane == 0) { s_pm[wid] = m; s_ps[wid] = ss; }
            }
            __syncthreads();
            if (wid == 0) {
                float mi = (lane < 16) ? s_pm[lane] : -INFINITY;
                float M = wmax(mi);
                float wg = (lane < 16) ? __expf(mi - M) : 0.f;
                if (lane < 16) s_wgt[lane] = wg;
                float sw = wsum((lane < 16) ? s_ps[lane] * wg : 0.f);
                if (lane == 0) { g_pm[b * 4 + part] = M; g_ps[b * 4 + part] = sw; }
            }
            if (part == 0 && tid >= 256) g_e0[b][tid - 256] = s_e[tid - 256];
            __syncthreads();
            {
                float acc = 0.f;
#pragma unroll
                for (int w = 0; w < 16; ++w)
                    acc += s_wgt[w] * s_pv[(w << 9) + tid];
                g_pvm[b][part][tid] = acc;
            }

            // ----- local sync among the 4 blocks of this batch -----
            __threadfence();
            __syncthreads();
            if (tid == 0) {
                atomicAdd(&g_bcnt[b], 1u);
                const unsigned tgt = 4u * (unsigned)(s + 1);
                while (((volatile unsigned*)g_bcnt)[b] < tgt) __nanosleep(16);
                __threadfence();
            }
            __syncthreads();

            // ----- merged P3: global merge, record, head (part0) -----
            if (wid == 0) {
                float mi = (lane < 4) ? ldcv(&g_pm[b * 4 + lane]) : -INFINITY;
                float M = wmax(mi);
                float wg = (lane < 4) ? __expf(mi - M) : 0.f;
                if (lane < 4) s_wgt[lane] = wg;
                float S = wsum((lane < 4) ? ldcv(&g_ps[b * 4 + lane]) * wg : 0.f);
                if (lane == 0) { s_MS[0] = M; s_MS[1] = __fdividef(1.f, S); }
            }
            __syncthreads();
            const float M = s_MS[0], invS = s_MS[1];
            float* rec = out_attn + ((size_t)s * Bq + b) * Tt;

            if (part != 0) {
                if (tid < 256)
                    rec[part * 256 + tid] = __expf(s_e[tid] - M) * invS;
                if (part == 1 && tid >= 256)
                    rec[tid - 256] = __expf(ldcv(&g_e0[b][tid - 256]) - M) * invS;
            } else {
                {
                    const int d = tid;
                    float acc = s_wgt[0] * ldcv(&g_pvm[b][0][d])
                              + s_wgt[1] * ldcv(&g_pvm[b][1][d])
                              + s_wgt[2] * ldcv(&g_pvm[b][2][d])
                              + s_wgt[3] * ldcv(&g_pvm[b][3][d]);
                    float ctx = acc * invS;
                    s_hc[Hh + d] = ctx;
                    g_xh2[b][d] = ctx;
                    s_hc[d] = s_h[d];
                }
                __syncthreads();
                {   // logits: 4 rows per warp, interleaved chains + packed reduce
                    ull C[16];
                    const ulonglong2* hc2 = (const ulonglong2*)s_hc;
#pragma unroll
                    for (int q = 0; q < 8; ++q) {
                        ulonglong2 t2 = hc2[lane + (q << 5)];
                        C[2 * q] = t2.x; C[2 * q + 1] = t2.y;
                    }
                    const int r0 = wid << 2;
                    const ulonglong2* wr0 = (const ulonglong2*)(W_out + (size_t)r0 * 2 * Hh);
                    ull e[4] = {0ull, 0ull, 0ull, 0ull};
#pragma unroll
                    for (int q = 0; q < 8; ++q) {
                        const int idx = lane + (q << 5);
#pragma unroll
                        for (int rr = 0; rr < 4; ++rr) {
                            ulonglong2 w2 = wr0[rr * 256 + idx];
                            e[rr] = fma2(w2.x, C[2 * q], e[rr]);
                            e[rr] = fma2(w2.y, C[2 * q + 1], e[rr]);
                        }
                    }
                    float v0, v1, v2, v3;
                    { float2 p = unpk(e[0]); v0 = p.x + p.y; }
                    { float2 p = unpk(e[1]); v1 = p.x + p.y; }
                    { float2 p = unpk(e[2]); v2 = p.x + p.y; }
                    { float2 p = unpk(e[3]); v3 = p.x + p.y; }
                    ull u01 = pk2(v0, v1), u23 = pk2(v2, v3);
#pragma unroll
                    for (int o = 16; o; o >>= 1) {
                        u01 = add2(u01, __shfl_xor_sync(0xffffffffu, u01, o));
                        u23 = add2(u23, __shfl_xor_sync(0xffffffffu, u23, o));
                    }
                    if (lane == 0) {
                        float2 p01 = unpk(u01), p23 = unpk(u23);
                        s_logits[r0]     = p01.x + b_out[r0];
                        s_logits[r0 + 1] = p01.y + b_out[r0 + 1];
                        s_logits[r0 + 2] = p23.x + b_out[r0 + 2];
                        s_logits[r0 + 3] = p23.y + b_out[r0 + 3];
                    }
                }
                __syncthreads();
                if (tid < 32) {
                    float z0 = s_logits[tid], z1 = s_logits[32 + tid];
                    // argmax FIRST (its max doubles as zm), publish early
                    float bv; int bi2;
                    if (z1 > z0) { bv = z1; bi2 = 32 + tid; } else { bv = z0; bi2 = tid; }
#pragma unroll
                    for (int o = 16; o; o >>= 1) {
                        float ov = __shfl_xor_sync(0xffffffffu, bv, o);
                        int   oi = __shfl_xor_sync(0xffffffffu, bi2, o);
                        if (ov > bv || (ov == bv && oi < bi2)) { bv = ov; bi2 = oi; }
                    }
                    if (tid == 0) g_argmax[b] = bi2;
                    const float zm = bv;                // max value from argmax
                    float es = wsum(__expf(z0 - zm) + __expf(z1 - zm));
                    float lse = zm + __logf(es);
                    float* lp = out_logp + ((size_t)s * Bq + b) * Vv;
                    lp[tid]      = z0 - lse;
                    lp[32 + tid] = z1 - lse;
                }
            }
        }
        ctx_sync(s, part);     // relaxed: wait only on the 32 ctx producers
    }
}

extern "C" void kernel_launch(void* const* d_in, const int* in_sizes, int n_in,
                              void* d_out, int out_size) {
    const float* L     = (const float*)d_in[0];
    const float* W_ih  = (const float*)d_in[1];
    const float* W_hh  = (const float*)d_in[2];
    const float* b_ih  = (const float*)d_in[3];
    const float* b_hh  = (const float*)d_in[4];
    const float* W_out = (const float*)d_in[5];
    const float* b_out = (const float*)d_in[6];
    float* out_logp = (float*)d_out;
    float* out_attn = (float*)d_out + (size_t)Ss * Bq * Vv;
    const int smem_bytes = SMEM_FLOATS * 4;
    cudaFuncSetAttribute(speller_kernel,
                         cudaFuncAttributeMaxDynamicSharedMemorySize, smem_bytes);
    speller_kernel<<<NBLK, NTHR, smem_bytes>>>(L, W_ih, W_hh, b_ih, b_hh,
                                               W_out, b_out, out_logp, out_attn);
}